// round 12
// baseline (speedup 1.0000x reference)
#include <cuda_runtime.h>
#include <math.h>

#define BB 8
#define CC 48
#define PP (BB*CC)          // 384 planes
#define N1 256
#define O1 133
#define O2 72
#define O3 41
#define HW (N1*N1)          // 65536
#define PIX3 (O3*O3)        // 1681
#define B3SZ (PP*PIX3)      // 645504

#define DLO_LIST { \
    -0.00107730108499558f, 0.004777257511010651f, 0.0005538422009938016f, \
    -0.031582039318031156f, 0.02752286553001629f, 0.09750160558707936f, \
    -0.12976686756709563f, -0.22626469396516913f, 0.3152503517092432f, \
    0.7511339080215775f, 0.4946238903983854f, 0.11154074335008017f }
#define DHI_LIST { \
    -0.11154074335008017f, 0.4946238903983854f, -0.7511339080215775f, \
    0.3152503517092432f, 0.22626469396516913f, -0.12976686756709563f, \
    -0.09750160558707936f, 0.02752286553001629f, 0.031582039318031156f, \
    0.0005538422009938016f, -0.004777257511010651f, -0.00107730108499558f }

typedef unsigned long long ull;

// ------------------- scratch arena (static device memory) -------------------
__device__ float g_h  [PP*HW];
__device__ float g_h1 [PP*HW];
__device__ float g_h2 [PP*HW];
__device__ float g_ll1[PP*O1*O1];
__device__ float g_lh1[PP*O1*O1];
__device__ float g_hl1[PP*O1*O1];
__device__ float g_hh1[PP*O1*O1];
__device__ float g_ll2[PP*O2*O2];
__device__ float g_lh2[PP*O2*O2];
__device__ float g_hl2[PP*O2*O2];
__device__ float g_hh2[PP*O2*O2];
__device__ float g_b3 [8*B3SZ];

// --------------------------- f32x2 packed helpers ---------------------------
__device__ __forceinline__ ull pack2(float x, float y) {
    ull r;
    asm("mov.b64 %0, {%1, %2};" : "=l"(r) : "f"(x), "f"(y));
    return r;
}
__device__ __forceinline__ void unpack2(ull v, float &x, float &y) {
    asm("mov.b64 {%0, %1}, %2;" : "=f"(x), "=f"(y) : "l"(v));
}
__device__ __forceinline__ ull ffma2(ull a, ull b, ull c) {
    ull d;
    asm("fma.rn.f32x2 %0, %1, %2, %3;" : "=l"(d) : "l"(a), "l"(b), "l"(c));
    return d;
}

__device__ __forceinline__ float gelu_f(float x) {
    return 0.5f * x * (1.0f + erff(x * 0.7071067811865475f));
}

__device__ __forceinline__ int reflect1(int i, int n) {
    i = (i < 0)  ? -1 - i : i;
    i = (i >= n) ? 2 * n - 1 - i : i;
    return i;
}

// ------------------------------ fc0 + pad -----------------------------------
__global__ void fc0_kernel(const float* __restrict__ x,
                           const float* __restrict__ w,
                           const float* __restrict__ b,
                           float* __restrict__ out) {
    int idx = blockIdx.x * blockDim.x + threadIdx.x;
    if (idx >= PP * HW) return;
    int p  = idx & (HW - 1);
    int pc = idx >> 16;
    int ch = pc % CC, bb = pc / CC;
    int r = p >> 8, c = p & 255;
    float v = 0.f;
    if (r < 255 && c < 255) {
        const float* xp = x + (((size_t)bb * 255 + r) * 255 + c) * 4;
        v = b[ch];
        #pragma unroll
        for (int i = 0; i < 4; i++) v += xp[i] * w[i * CC + ch];
    }
    out[idx] = v;
}

// ---------------------- fused 2D analysis (row then col) --------------------
template<int NR, int NC, int OR, int OC, int PADR, int K, int CH, int THREADS>
__global__ void __launch_bounds__(THREADS) afb2d(
    const float* __restrict__ in, long in_ps, int in_rs,
    float* __restrict__ ll, float* __restrict__ lh,
    float* __restrict__ hl, float* __restrict__ hh)
{
    constexpr int PW    = NC + 10 + PADR;
    constexpr int PWP   = (PW + 3) & ~1;
    constexpr int ROWS  = 2 * K + 11;
    constexpr int PITCH = (OC + 1) & ~1;
    constexpr int NPAIR = (OC + 1) / 2;
    constexpr long OPS  = (long)OR * OC;
    extern __shared__ float smem[];
    float* sIn = smem;                       // CH * PWP
    float* sLo = smem + CH * PWP;            // ROWS * PITCH
    float* sHi = sLo + ROWS * PITCH;         // ROWS * PITCH
    const float dlo[12] = DLO_LIST;
    const float dhi[12] = DHI_LIST;

    int p   = blockIdx.y;
    int k0  = blockIdx.x * K;
    int rbase = 2 * k0 - 10;
    int tid = threadIdx.x;
    const float* ip = in + (size_t)p * in_ps;

    for (int c0 = 0; c0 < ROWS; c0 += CH) {
        __syncthreads();
        for (int e = tid; e < CH * PW; e += THREADS) {
            int j = e / PW, c = e - j * PW;
            int rr = reflect1(rbase + c0 + j, NR);
            int cc = reflect1(c - 10, NC);
            sIn[j * PWP + c] = ip[(size_t)rr * in_rs + cc];
        }
        __syncthreads();
        for (int e = tid; e < CH * NPAIR; e += THREADS) {
            int j = e / NPAIR, t = e - j * NPAIR;
            int row = c0 + j;
            if (row < ROWS) {
                float v[14];
                const float2* sp = (const float2*)(sIn + j * PWP + 4 * t);
                #pragma unroll
                for (int m = 0; m < 7; m++) {
                    float2 q = sp[m];
                    v[2*m] = q.x; v[2*m+1] = q.y;
                }
                float ale = 0.f, ahe = 0.f, alo = 0.f, aho = 0.f;
                #pragma unroll
                for (int jj = 0; jj < 12; jj++) {
                    ale += v[jj]     * dlo[11 - jj];
                    ahe += v[jj]     * dhi[11 - jj];
                    alo += v[jj + 2] * dlo[11 - jj];
                    aho += v[jj + 2] * dhi[11 - jj];
                }
                sLo[row * PITCH + 2*t]     = ale;
                sHi[row * PITCH + 2*t]     = ahe;
                sLo[row * PITCH + 2*t + 1] = alo;
                sHi[row * PITCH + 2*t + 1] = aho;
            }
        }
    }
    __syncthreads();
    // col transform: 2 columns per item, f32x2 FMA with broadcast coeff pairs
    ull clo[12], chi[12];
    #pragma unroll
    for (int t = 0; t < 12; t++) {
        clo[t] = pack2(dlo[11 - t], dlo[11 - t]);
        chi[t] = pack2(dhi[11 - t], dhi[11 - t]);
    }
    for (int e = tid; e < K * NPAIR; e += THREADS) {
        int k = e / NPAIR, cp = e - k * NPAIR;
        int kg = k0 + k;
        if (kg < OR) {
            int c = 2 * cp;
            ull all = 0, alh = 0, ahl = 0, ahh = 0;
            #pragma unroll
            for (int t = 0; t < 12; t++) {
                ull a = *(const ull*)&sLo[(2*k + t) * PITCH + c];
                ull b = *(const ull*)&sHi[(2*k + t) * PITCH + c];
                all = ffma2(a, clo[t], all);
                alh = ffma2(a, chi[t], alh);
                ahl = ffma2(b, clo[t], ahl);
                ahh = ffma2(b, chi[t], ahh);
            }
            float x0, x1;
            size_t o = (size_t)p * OPS + (size_t)kg * OC + c;
            unpack2(all, x0, x1); ll[o] = x0; if (c + 1 < OC) ll[o+1] = x1;
            unpack2(alh, x0, x1); lh[o] = x0; if (c + 1 < OC) lh[o+1] = x1;
            unpack2(ahl, x0, x1); hl[o] = x0; if (c + 1 < OC) hl[o+1] = x1;
            unpack2(ahh, x0, x1); hh[o] = x0; if (c + 1 < OC) hh[o+1] = x1;
        }
    }
}

// ---------------------- fused 2D synthesis (col then row) -------------------
template<int NIN, int M, int KO, int THREADS>
__global__ void __launch_bounds__(THREADS) sfb2d(
    const float* __restrict__ bll, long ll_ps, int ll_rs,
    const float* __restrict__ blh, const float* __restrict__ bhl,
    const float* __restrict__ bhh, long b_ps,
    float* __restrict__ out)
{
    constexpr int W    = 2 * M - 10;
    constexpr int W2   = 2 * NIN - 10;
    constexpr int RIN  = KO / 2 + 6;
    constexpr int MP   = (M + 1) & ~1;
    constexpr int CP   = (M + 1) / 2;
    constexpr int UP   = M - 5;
    constexpr int UP2  = (UP + 1) / 2;
    constexpr int SLSZ = KO * MP + 8;     // +8 slack for 2-u row reads
    extern __shared__ float smem[];
    float* s0 = smem;                  // RIN*MP each
    float* s1 = s0 + RIN * MP;
    float* s2 = s1 + RIN * MP;
    float* s3 = s2 + RIN * MP;
    float* sl = s3 + RIN * MP;         // SLSZ each
    float* sh = sl + SLSZ;
    const float dlo[12] = DLO_LIST;
    const float dhi[12] = DHI_LIST;

    int p  = blockIdx.y;
    int j0 = blockIdx.x * KO;
    int r0 = j0 >> 1;
    int tid = threadIdx.x;
    const float* pll = bll + (size_t)p * ll_ps;
    const float* plh = blh + (size_t)p * b_ps;
    const float* phl = bhl + (size_t)p * b_ps;
    const float* phh = bhh + (size_t)p * b_ps;

    for (int e = tid; e < RIN * M; e += THREADS) {
        int r = e / M, c = e - r * M;
        int rr = r0 + r; rr = (rr > NIN - 1) ? NIN - 1 : rr;
        int se = r * MP + c;
        s0[se] = pll[(size_t)rr * ll_rs + c];
        s1[se] = plh[(size_t)rr * M + c];
        s2[se] = phl[(size_t)rr * M + c];
        s3[se] = phh[(size_t)rr * M + c];
    }
    __syncthreads();
    // column synthesis: 2 cols per item, f32x2 FMA
    {
        ull ce[6], co[6], de[6], dq[6];
        #pragma unroll
        for (int kk = 0; kk < 6; kk++) {
            ce[kk] = pack2(dlo[2*kk+1], dlo[2*kk+1]);
            co[kk] = pack2(dlo[2*kk],   dlo[2*kk]);
            de[kk] = pack2(dhi[2*kk+1], dhi[2*kk+1]);
            dq[kk] = pack2(dhi[2*kk],   dhi[2*kk]);
        }
        for (int e = tid; e < (KO/2) * CP; e += THREADS) {
            int uj = e / CP, cp = e - uj * CP;
            int c = 2 * cp;
            ull el = 0, ol = 0, eh = 0, oh = 0;
            #pragma unroll
            for (int kk = 0; kk < 6; kk++) {
                int sb = (uj + kk) * MP + c;
                ull a  = *(const ull*)&s0[sb];
                ull b  = *(const ull*)&s1[sb];
                ull g  = *(const ull*)&s2[sb];
                ull hq = *(const ull*)&s3[sb];
                el = ffma2(a, ce[kk], el); el = ffma2(b, de[kk], el);
                ol = ffma2(a, co[kk], ol); ol = ffma2(b, dq[kk], ol);
                eh = ffma2(g, ce[kk], eh); eh = ffma2(hq, de[kk], eh);
                oh = ffma2(g, co[kk], oh); oh = ffma2(hq, dq[kk], oh);
            }
            int sb0 = (2*uj) * MP + c, sb1 = sb0 + MP;
            *(ull*)&sl[sb0] = el;
            *(ull*)&sl[sb1] = ol;
            *(ull*)&sh[sb0] = eh;
            *(ull*)&sh[sb1] = oh;
        }
    }
    __syncthreads();
    // row synthesis: 2 output-pairs per item (u0 = 2q, u1 = 2q+1)
    {
        ull CL[6], CHc[6];
        #pragma unroll
        for (int kk = 0; kk < 6; kk++) {
            CL[kk]  = pack2(dlo[2*kk+1], dlo[2*kk]);   // (even, odd) lo coeffs
            CHc[kk] = pack2(dhi[2*kk+1], dhi[2*kk]);
        }
        for (int e = tid; e < KO * UP2; e += THREADS) {
            int j = e / UP2, q = e - j * UP2;
            int jg = j0 + j;
            if (jg < W2) {
                int base = j * MP + 2 * q;
                float a[8], b[8];
                #pragma unroll
                for (int m = 0; m < 4; m++) {
                    float2 fa = *(const float2*)&sl[base + 2*m];
                    float2 fb = *(const float2*)&sh[base + 2*m];
                    a[2*m] = fa.x; a[2*m+1] = fa.y;
                    b[2*m] = fb.x; b[2*m+1] = fb.y;
                }
                ull pa[7], pb[7];
                #pragma unroll
                for (int i = 0; i < 7; i++) {
                    pa[i] = pack2(a[i], a[i]);
                    pb[i] = pack2(b[i], b[i]);
                }
                ull acc0 = 0, acc1 = 0;     // (ev, od) for u0, u1
                #pragma unroll
                for (int kk = 0; kk < 6; kk++) {
                    acc0 = ffma2(pa[kk],   CL[kk],  acc0);
                    acc0 = ffma2(pb[kk],   CHc[kk], acc0);
                    acc1 = ffma2(pa[kk+1], CL[kk],  acc1);
                    acc1 = ffma2(pb[kk+1], CHc[kk], acc1);
                }
                int u0 = 2 * q;
                size_t ob = ((size_t)p * W2 + jg) * W + 2 * u0;
                float ev, od;
                unpack2(acc0, ev, od);
                *(float2*)&out[ob] = make_float2(ev, od);
                if (u0 + 1 < UP) {
                    unpack2(acc1, ev, od);
                    *(float2*)&out[ob + 2] = make_float2(ev, od);
                }
            }
        }
    }
}

// --------------------- per-pixel 48x48 channel mix (41x41) ------------------
__global__ void mix_kernel(const float* __restrict__ b3in, const float* __restrict__ w,
                           float* __restrict__ b3out) {
    __shared__ float ts[384 * 18];
    __shared__ float ws[4 * 48 * 18];
    int px0 = blockIdx.x * 16;
    int band = blockIdx.y;
    int tid = threadIdx.x;
    for (int e = tid; e < 384 * 16; e += 384) {
        int plane = e >> 4, px = e & 15;
        int gp = px0 + px;
        ts[plane * 18 + px] = (gp < PIX3)
            ? b3in[(size_t)band * B3SZ + (size_t)plane * PIX3 + gp] : 0.f;
    }
    int b = tid / 48, o = tid - b * 48;
    ull acc[8];
    #pragma unroll
    for (int m = 0; m < 8; m++) acc[m] = 0ull;
    const float* wband = w + (size_t)band * 2304 * PIX3;
    for (int ic = 0; ic < 12; ic++) {
        __syncthreads();
        for (int e = tid; e < 3072; e += 384) {
            int ii = e / 768;
            int rem = e - ii * 768;
            int oo = rem >> 4, px = rem & 15;
            int gp = px0 + px;
            ws[(ii * 48 + oo) * 18 + px] = (gp < PIX3)
                ? wband[((size_t)(ic * 4 + ii) * 48 + oo) * PIX3 + gp] : 0.f;
        }
        __syncthreads();
        #pragma unroll
        for (int i = 0; i < 4; i++) {
            const ull* tr = (const ull*)(ts + (b * 48 + ic * 4 + i) * 18);
            const ull* wr = (const ull*)(ws + (i * 48 + o) * 18);
            #pragma unroll
            for (int m = 0; m < 8; m++) acc[m] = ffma2(tr[m], wr[m], acc[m]);
        }
    }
    size_t obase = (size_t)band * B3SZ + (size_t)(b * 48 + o) * PIX3 + px0;
    #pragma unroll
    for (int m = 0; m < 8; m++) {
        float x, y;
        unpack2(acc[m], x, y);
        int gp0 = px0 + 2 * m;
        if (gp0 < PIX3)     b3out[obase + 2 * m]     = x;
        if (gp0 + 1 < PIX3) b3out[obase + 2 * m + 1] = y;
    }
}

// ------------------ pointwise conv + residual add + gelu --------------------
__global__ void pw_kernel(float* __restrict__ h, const float* __restrict__ h2,
                          const float* __restrict__ cw, const float* __restrict__ cb,
                          int do_gelu) {
    __shared__ ull ws2[2304];
    __shared__ float bs[48];
    int tid = threadIdx.x;
    for (int j = tid; j < 2304; j += 256) {
        int o = j / 48, i = j - o * 48;
        float w = cw[j];
        ws2[i * 48 + o] = pack2(w, w);
    }
    if (tid < 48) bs[tid] = cb[tid];
    __syncthreads();
    int og = tid >> 6;
    int pq = tid & 63;
    int bx = blockIdx.x;
    int bb = bx >> 8;
    int p0 = ((bx & 255) << 8) + (pq << 2);
    size_t base = ((size_t)bb * CC) * HW + p0;
    ull acc[12][2];
    #pragma unroll
    for (int o = 0; o < 12; o++) {
        float b = bs[og * 12 + o];
        acc[o][0] = pack2(b, b);
        acc[o][1] = acc[o][0];
    }
    for (int i = 0; i < 48; i++) {
        ulonglong2 v = *(const ulonglong2*)(h + base + (size_t)i * HW);
        #pragma unroll
        for (int o = 0; o < 12; o++) {
            ull w2 = ws2[i * 48 + og * 12 + o];
            acc[o][0] = ffma2(v.x, w2, acc[o][0]);
            acc[o][1] = ffma2(v.y, w2, acc[o][1]);
        }
    }
    __syncthreads();
    #pragma unroll
    for (int o = 0; o < 12; o++) {
        int oc = og * 12 + o;
        float4 r = *(const float4*)(h2 + base + (size_t)oc * HW);
        float a, b, c, d;
        unpack2(acc[o][0], a, b);
        unpack2(acc[o][1], c, d);
        a += r.x; b += r.y; c += r.z; d += r.w;
        if (do_gelu) { a = gelu_f(a); b = gelu_f(b); c = gelu_f(c); d = gelu_f(d); }
        *(float4*)(h + base + (size_t)oc * HW) = make_float4(a, b, c, d);
    }
}

// -------------------------- fused fc1+gelu+fc2 head --------------------------
__global__ void head_kernel(const float* __restrict__ h, const float* __restrict__ w1,
                            const float* __restrict__ b1, const float* __restrict__ w2,
                            const float* __restrict__ b2, float* __restrict__ out) {
    __shared__ ull w1s[1536];
    __shared__ float b1s[64];
    __shared__ float w2s[64];
    int tid = threadIdx.x;
    const ull* w1u = (const ull*)w1;
    for (int j = tid; j < 1536; j += 256) w1s[j] = w1u[j];
    if (tid < 64) { b1s[tid] = b1[tid]; w2s[tid] = w2[tid]; }
    __syncthreads();
    int q = blockIdx.x * 256 + tid;
    if (q >= 8 * 255 * 255) return;
    int c = q % 255;
    int t2 = q / 255;
    int r = t2 % 255;
    int bb = t2 / 255;
    size_t base = ((size_t)bb * CC) * HW + (size_t)r * 256 + c;
    ull acc[32];
    #pragma unroll
    for (int j = 0; j < 32; j++) acc[j] = pack2(b1s[2 * j], b1s[2 * j + 1]);
    for (int i = 0; i < 48; i++) {
        float v = h[base + (size_t)i * HW];
        ull vv = pack2(v, v);
        #pragma unroll
        for (int j = 0; j < 32; j++) acc[j] = ffma2(vv, w1s[i * 32 + j], acc[j]);
    }
    float o = b2[0];
    #pragma unroll
    for (int j = 0; j < 32; j++) {
        float a, b;
        unpack2(acc[j], a, b);
        o += gelu_f(a) * w2s[2 * j] + gelu_f(b) * w2s[2 * j + 1];
    }
    out[q] = o;
}

// ---------------------------------- launch ----------------------------------
static inline int grd(long n, int bs) { return (int)((n + bs - 1) / bs); }

// smem sizes (bytes) matching template constexpr math (R8 config + SL slack)
#define AFB1_SMEM ((7*278 + 2*63*134) * 4)          // 75320
#define AFB2_SMEM ((5*156 + 2*59*72) * 4)           // 37104
#define AFB3_SMEM ((53*94 + 2*53*42) * 4)           // 37736
#define SFB3_SMEM ((4*24*42 + 2*(36*42+8)) * 4)     // 28288
#define SFB2_SMEM ((4*23*72 + 2*(34*72+8)) * 4)     // 46144
#define SFB1_SMEM ((4*22*134 + 2*(32*134+8)) * 4)   // 81536

extern "C" void kernel_launch(void* const* d_in, const int* in_sizes, int n_in,
                              void* d_out, int out_size) {
    const float* x     = (const float*)d_in[0];
    const float* fc0_w = (const float*)d_in[1];
    const float* fc0_b = (const float*)d_in[2];
    const float* wc[4] = { (const float*)d_in[3], (const float*)d_in[4],
                           (const float*)d_in[5], (const float*)d_in[6] };
    const float* cw    = (const float*)d_in[7];
    const float* cb    = (const float*)d_in[8];
    const float* fc1_w = (const float*)d_in[9];
    const float* fc1_b = (const float*)d_in[10];
    const float* fc2_w = (const float*)d_in[11];
    const float* fc2_b = (const float*)d_in[12];
    float* out = (float*)d_out;

    float *h, *h1, *h2, *ll1, *lh1, *hl1, *hh1, *ll2, *lh2, *hl2, *hh2, *b3;
    cudaGetSymbolAddress((void**)&h,   g_h);
    cudaGetSymbolAddress((void**)&h1,  g_h1);
    cudaGetSymbolAddress((void**)&h2,  g_h2);
    cudaGetSymbolAddress((void**)&ll1, g_ll1);
    cudaGetSymbolAddress((void**)&lh1, g_lh1);
    cudaGetSymbolAddress((void**)&hl1, g_hl1);
    cudaGetSymbolAddress((void**)&hh1, g_hh1);
    cudaGetSymbolAddress((void**)&ll2, g_ll2);
    cudaGetSymbolAddress((void**)&lh2, g_lh2);
    cudaGetSymbolAddress((void**)&hl2, g_hl2);
    cudaGetSymbolAddress((void**)&hh2, g_hh2);
    cudaGetSymbolAddress((void**)&b3,  g_b3);

    cudaFuncSetAttribute(afb2d<256,256,133,133,10,26,7,256>,
                         cudaFuncAttributeMaxDynamicSharedMemorySize, AFB1_SMEM);
    cudaFuncSetAttribute(sfb2d<133,133,32,512>,
                         cudaFuncAttributeMaxDynamicSharedMemorySize, SFB1_SMEM);

    fc0_kernel<<<grd((long)PP * HW, 256), 256>>>(x, fc0_w, fc0_b, h);

    for (int layer = 0; layer < 4; layer++) {
        // ---------------- forward DWT (3 fused levels) ----------------
        afb2d<256,256,133,133,10,26,7,256><<<dim3(6, PP), 256, AFB1_SMEM>>>(
            h, (long)HW, 256, ll1, lh1, hl1, hh1);
        afb2d<133,133,72,72,11,24,5,256><<<dim3(3, PP), 256, AFB2_SMEM>>>(
            ll1, 133L*133, 133, ll2, lh2, hl2, hh2);
        afb2d<72,72,41,41,10,21,53,256><<<dim3(2, PP), 256, AFB3_SMEM>>>(
            ll2, 72L*72, 72,
            b3 + 0L*B3SZ, b3 + 1L*B3SZ, b3 + 2L*B3SZ, b3 + 3L*B3SZ);

        // ---------------- coarsest-level channel mix ----------------
        mix_kernel<<<dim3(grd(PIX3,16), 4), 384>>>(b3, wc[layer], b3 + 4L*B3SZ);

        // ---------------- inverse DWT (3 fused levels) ----------------
        sfb2d<41,41,36,256><<<dim3(2, PP), 256, SFB3_SMEM>>>(
            b3 + 4L*B3SZ, (long)PIX3, 41,
            b3 + 5L*B3SZ, b3 + 6L*B3SZ, b3 + 7L*B3SZ, (long)PIX3, ll2);
        sfb2d<72,72,34,256><<<dim3(4, PP), 256, SFB2_SMEM>>>(
            ll2, 72L*72, 72, lh2, hl2, hh2, 72L*72, h1);
        sfb2d<133,133,32,512><<<dim3(8, PP), 512, SFB1_SMEM>>>(
            h1, 134L*134, 134, lh1, hl1, hh1, 133L*133, h2);

        // ---------------- pointwise conv + add + gelu ----------------
        pw_kernel<<<2048, 256>>>(h, h2, cw + (size_t)layer * 2304,
                                 cb + (size_t)layer * 48, layer < 3 ? 1 : 0);
    }

    head_kernel<<<grd(8L * 255 * 255, 256), 256>>>(h, fc1_w, fc1_b, fc2_w, fc2_b, out);
}

// round 13
// speedup vs baseline: 1.1368x; 1.1368x over previous
#include <cuda_runtime.h>
#include <math.h>

#define BB 8
#define CC 48
#define PP (BB*CC)          // 384 planes
#define N1 256
#define O1 133
#define O2 72
#define O3 41
#define HW (N1*N1)          // 65536
#define PIX3 (O3*O3)        // 1681
#define B3SZ (PP*PIX3)      // 645504

#define DLO_LIST { \
    -0.00107730108499558f, 0.004777257511010651f, 0.0005538422009938016f, \
    -0.031582039318031156f, 0.02752286553001629f, 0.09750160558707936f, \
    -0.12976686756709563f, -0.22626469396516913f, 0.3152503517092432f, \
    0.7511339080215775f, 0.4946238903983854f, 0.11154074335008017f }
#define DHI_LIST { \
    -0.11154074335008017f, 0.4946238903983854f, -0.7511339080215775f, \
    0.3152503517092432f, 0.22626469396516913f, -0.12976686756709563f, \
    -0.09750160558707936f, 0.02752286553001629f, 0.031582039318031156f, \
    0.0005538422009938016f, -0.004777257511010651f, -0.00107730108499558f }

// ------------------- scratch arena (static device memory) -------------------
__device__ float g_h  [PP*HW];
__device__ float g_h1 [PP*HW];      // 134x134 IDWT intermediate (L2 out)
__device__ float g_h2 [PP*HW];      // L1 synthesis output (pre-pointwise)
__device__ float g_ll1[PP*O1*O1];
__device__ float g_lh1[PP*O1*O1];
__device__ float g_hl1[PP*O1*O1];
__device__ float g_hh1[PP*O1*O1];
__device__ float g_ll2[PP*O2*O2];
__device__ float g_lh2[PP*O2*O2];
__device__ float g_hl2[PP*O2*O2];
__device__ float g_hh2[PP*O2*O2];
__device__ float g_b3 [8*B3SZ];

// --------------------------- f32x2 packed helpers ---------------------------
__device__ __forceinline__ unsigned long long pack2(float x, float y) {
    unsigned long long r;
    asm("mov.b64 %0, {%1, %2};" : "=l"(r) : "f"(x), "f"(y));
    return r;
}
__device__ __forceinline__ void unpack2(unsigned long long v, float &x, float &y) {
    asm("mov.b64 {%0, %1}, %2;" : "=f"(x), "=f"(y) : "l"(v));
}
__device__ __forceinline__ unsigned long long ffma2(unsigned long long a,
                                                    unsigned long long b,
                                                    unsigned long long c) {
    unsigned long long d;
    asm("fma.rn.f32x2 %0, %1, %2, %3;" : "=l"(d) : "l"(a), "l"(b), "l"(c));
    return d;
}

__device__ __forceinline__ float gelu_f(float x) {
    return 0.5f * x * (1.0f + erff(x * 0.7071067811865475f));
}

__device__ __forceinline__ int reflect1(int i, int n) {
    i = (i < 0)  ? -1 - i : i;
    i = (i >= n) ? 2 * n - 1 - i : i;
    return i;
}

// ------------------------------ fc0 + pad -----------------------------------
__global__ void fc0_kernel(const float* __restrict__ x,
                           const float* __restrict__ w,
                           const float* __restrict__ b,
                           float* __restrict__ out) {
    int idx = blockIdx.x * blockDim.x + threadIdx.x;
    if (idx >= PP * HW) return;
    int p  = idx & (HW - 1);
    int pc = idx >> 16;
    int ch = pc % CC, bb = pc / CC;
    int r = p >> 8, c = p & 255;
    float v = 0.f;
    if (r < 255 && c < 255) {
        const float* xp = x + (((size_t)bb * 255 + r) * 255 + c) * 4;
        v = b[ch];
        #pragma unroll
        for (int i = 0; i < 4; i++) v += xp[i] * w[i * CC + ch];
    }
    out[idx] = v;
}

// ---------------------- fused 2D analysis (row then col) --------------------
template<int NR, int NC, int OR, int OC, int PADR, int K, int CH, int THREADS>
__global__ void __launch_bounds__(THREADS) afb2d(
    const float* __restrict__ in, long in_ps, int in_rs,
    float* __restrict__ ll, float* __restrict__ lh,
    float* __restrict__ hl, float* __restrict__ hh)
{
    constexpr int PW    = NC + 10 + PADR;
    constexpr int PWP   = (PW + 3) & ~1;
    constexpr int ROWS  = 2 * K + 11;
    constexpr int PITCH = (OC + 1) & ~1;
    constexpr int NPAIR = (OC + 1) / 2;
    constexpr long OPS  = (long)OR * OC;
    extern __shared__ float smem[];
    float* sIn = smem;                       // CH * PWP
    float* sLo = smem + CH * PWP;            // ROWS * PITCH
    float* sHi = sLo + ROWS * PITCH;         // ROWS * PITCH
    const float dlo[12] = DLO_LIST;
    const float dhi[12] = DHI_LIST;

    int p   = blockIdx.y;
    int k0  = blockIdx.x * K;
    int rbase = 2 * k0 - 10;
    int tid = threadIdx.x;
    const float* ip = in + (size_t)p * in_ps;

    for (int c0 = 0; c0 < ROWS; c0 += CH) {
        __syncthreads();
        for (int e = tid; e < CH * PW; e += THREADS) {
            int j = e / PW, c = e - j * PW;
            int rr = reflect1(rbase + c0 + j, NR);
            int cc = reflect1(c - 10, NC);
            sIn[j * PWP + c] = ip[(size_t)rr * in_rs + cc];
        }
        __syncthreads();
        for (int e = tid; e < CH * NPAIR; e += THREADS) {
            int j = e / NPAIR, t = e - j * NPAIR;
            int row = c0 + j;
            if (row < ROWS) {
                float v[14];
                const float2* sp = (const float2*)(sIn + j * PWP + 4 * t);
                #pragma unroll
                for (int m = 0; m < 7; m++) {
                    float2 q = sp[m];
                    v[2*m] = q.x; v[2*m+1] = q.y;
                }
                float ale = 0.f, ahe = 0.f, alo = 0.f, aho = 0.f;
                #pragma unroll
                for (int jj = 0; jj < 12; jj++) {
                    ale += v[jj]     * dlo[11 - jj];
                    ahe += v[jj]     * dhi[11 - jj];
                    alo += v[jj + 2] * dlo[11 - jj];
                    aho += v[jj + 2] * dhi[11 - jj];
                }
                sLo[row * PITCH + 2*t]     = ale;
                sHi[row * PITCH + 2*t]     = ahe;
                sLo[row * PITCH + 2*t + 1] = alo;
                sHi[row * PITCH + 2*t + 1] = aho;
            }
        }
    }
    __syncthreads();
    for (int e = tid; e < K * NPAIR; e += THREADS) {
        int k = e / NPAIR, cp = e - k * NPAIR;
        int kg = k0 + k;
        if (kg < OR) {
            int c = 2 * cp;
            float a0x=0,a0y=0,a1x=0,a1y=0,a2x=0,a2y=0,a3x=0,a3y=0;
            #pragma unroll
            for (int t = 0; t < 12; t++) {
                float2 a = *(const float2*)&sLo[(2*k + t) * PITCH + c];
                float2 b = *(const float2*)&sHi[(2*k + t) * PITCH + c];
                a0x += a.x * dlo[11-t]; a0y += a.y * dlo[11-t];
                a1x += a.x * dhi[11-t]; a1y += a.y * dhi[11-t];
                a2x += b.x * dlo[11-t]; a2y += b.y * dlo[11-t];
                a3x += b.x * dhi[11-t]; a3y += b.y * dhi[11-t];
            }
            size_t o = (size_t)p * OPS + (size_t)kg * OC + c;
            ll[o] = a0x; lh[o] = a1x; hl[o] = a2x; hh[o] = a3x;
            if (c + 1 < OC) {
                ll[o+1] = a0y; lh[o+1] = a1y; hl[o+1] = a2y; hh[o+1] = a3y;
            }
        }
    }
}

// ---------------------- fused 2D synthesis (col then row) -------------------
template<int NIN, int M, int KO, int THREADS>
__global__ void __launch_bounds__(THREADS) sfb2d(
    const float* __restrict__ bll, long ll_ps, int ll_rs,
    const float* __restrict__ blh, const float* __restrict__ bhl,
    const float* __restrict__ bhh, long b_ps,
    float* __restrict__ out)
{
    constexpr int W   = 2 * M - 10;
    constexpr int W2  = 2 * NIN - 10;
    constexpr int RIN = KO / 2 + 6;
    constexpr int MP  = (M + 1) & ~1;
    constexpr int CP  = (M + 1) / 2;
    constexpr int UP  = M - 5;
    extern __shared__ float smem[];
    float* s0 = smem;                  // RIN*MP each
    float* s1 = s0 + RIN * MP;
    float* s2 = s1 + RIN * MP;
    float* s3 = s2 + RIN * MP;
    float* sl = s3 + RIN * MP;         // KO*MP each
    float* sh = sl + KO * MP;
    const float dlo[12] = DLO_LIST;
    const float dhi[12] = DHI_LIST;

    int p  = blockIdx.y;
    int j0 = blockIdx.x * KO;
    int r0 = j0 >> 1;
    int tid = threadIdx.x;
    const float* pll = bll + (size_t)p * ll_ps;
    const float* plh = blh + (size_t)p * b_ps;
    const float* phl = bhl + (size_t)p * b_ps;
    const float* phh = bhh + (size_t)p * b_ps;

    for (int e = tid; e < RIN * M; e += THREADS) {
        int r = e / M, c = e - r * M;
        int rr = r0 + r; rr = (rr > NIN - 1) ? NIN - 1 : rr;
        int se = r * MP + c;
        s0[se] = pll[(size_t)rr * ll_rs + c];
        s1[se] = plh[(size_t)rr * M + c];
        s2[se] = phl[(size_t)rr * M + c];
        s3[se] = phh[(size_t)rr * M + c];
    }
    __syncthreads();
    for (int e = tid; e < (KO/2) * CP; e += THREADS) {
        int uj = e / CP, cp = e - uj * CP;
        int c = 2 * cp;
        float elx=0,ely=0,olx=0,oly=0,ehx=0,ehy=0,ohx=0,ohy=0;
        #pragma unroll
        for (int kk = 0; kk < 6; kk++) {
            int sb = (uj + kk) * MP + c;
            float2 a  = *(const float2*)&s0[sb];
            float2 b  = *(const float2*)&s1[sb];
            float2 g  = *(const float2*)&s2[sb];
            float2 hq = *(const float2*)&s3[sb];
            float ce = dlo[2*kk+1], co = dlo[2*kk];
            float de = dhi[2*kk+1], dq = dhi[2*kk];
            elx += a.x*ce + b.x*de;   ely += a.y*ce + b.y*de;
            olx += a.x*co + b.x*dq;   oly += a.y*co + b.y*dq;
            ehx += g.x*ce + hq.x*de;  ehy += g.y*ce + hq.y*de;
            ohx += g.x*co + hq.x*dq;  ohy += g.y*co + hq.y*dq;
        }
        int sb0 = (2*uj) * MP + c, sb1 = (2*uj + 1) * MP + c;
        sl[sb0] = elx; sl[sb1] = olx; sh[sb0] = ehx; sh[sb1] = ohx;
        if (c + 1 < M) {
            sl[sb0+1] = ely; sl[sb1+1] = oly; sh[sb0+1] = ehy; sh[sb1+1] = ohy;
        }
    }
    __syncthreads();
    for (int e = tid; e < KO * UP; e += THREADS) {
        int j = e / UP, u = e - j * UP;
        int jg = j0 + j;
        if (jg < W2) {
            float ev = 0.f, od = 0.f;
            #pragma unroll
            for (int kk = 0; kk < 6; kk++) {
                float a = sl[j * MP + u + kk], b = sh[j * MP + u + kk];
                ev += a * dlo[2*kk+1] + b * dhi[2*kk+1];
                od += a * dlo[2*kk]   + b * dhi[2*kk];
            }
            *(float2*)&out[((size_t)p * W2 + jg) * W + 2*u] = make_float2(ev, od);
        }
    }
}

// --------------------- per-pixel 48x48 channel mix (41x41) ------------------
__global__ void mix_kernel(const float* __restrict__ b3in, const float* __restrict__ w,
                           float* __restrict__ b3out) {
    __shared__ float ts[384 * 18];
    __shared__ float ws[4 * 48 * 18];
    int px0 = blockIdx.x * 16;
    int band = blockIdx.y;
    int tid = threadIdx.x;
    for (int e = tid; e < 384 * 16; e += 384) {
        int plane = e >> 4, px = e & 15;
        int gp = px0 + px;
        ts[plane * 18 + px] = (gp < PIX3)
            ? b3in[(size_t)band * B3SZ + (size_t)plane * PIX3 + gp] : 0.f;
    }
    int b = tid / 48, o = tid - b * 48;
    unsigned long long acc[8];
    #pragma unroll
    for (int m = 0; m < 8; m++) acc[m] = 0ull;
    const float* wband = w + (size_t)band * 2304 * PIX3;
    for (int ic = 0; ic < 12; ic++) {
        __syncthreads();
        for (int e = tid; e < 3072; e += 384) {
            int ii = e / 768;
            int rem = e - ii * 768;
            int oo = rem >> 4, px = rem & 15;
            int gp = px0 + px;
            ws[(ii * 48 + oo) * 18 + px] = (gp < PIX3)
                ? wband[((size_t)(ic * 4 + ii) * 48 + oo) * PIX3 + gp] : 0.f;
        }
        __syncthreads();
        #pragma unroll
        for (int i = 0; i < 4; i++) {
            const unsigned long long* tr =
                (const unsigned long long*)(ts + (b * 48 + ic * 4 + i) * 18);
            const unsigned long long* wr =
                (const unsigned long long*)(ws + (i * 48 + o) * 18);
            #pragma unroll
            for (int m = 0; m < 8; m++) acc[m] = ffma2(tr[m], wr[m], acc[m]);
        }
    }
    size_t obase = (size_t)band * B3SZ + (size_t)(b * 48 + o) * PIX3 + px0;
    #pragma unroll
    for (int m = 0; m < 8; m++) {
        float x, y;
        unpack2(acc[m], x, y);
        int gp0 = px0 + 2 * m;
        if (gp0 < PIX3)     b3out[obase + 2 * m]     = x;
        if (gp0 + 1 < PIX3) b3out[obase + 2 * m + 1] = y;
    }
}

// ------------------ pointwise conv + residual add + gelu --------------------
__global__ void pw_kernel(float* __restrict__ h, const float* __restrict__ h2,
                          const float* __restrict__ cw, const float* __restrict__ cb,
                          int do_gelu) {
    __shared__ unsigned long long ws2[2304];
    __shared__ float bs[48];
    int tid = threadIdx.x;
    for (int j = tid; j < 2304; j += 256) {
        int o = j / 48, i = j - o * 48;
        float w = cw[j];
        ws2[i * 48 + o] = pack2(w, w);
    }
    if (tid < 48) bs[tid] = cb[tid];
    __syncthreads();
    int og = tid >> 6;
    int pq = tid & 63;
    int bx = blockIdx.x;
    int bb = bx >> 8;
    int p0 = ((bx & 255) << 8) + (pq << 2);
    size_t base = ((size_t)bb * CC) * HW + p0;
    unsigned long long acc[12][2];
    #pragma unroll
    for (int o = 0; o < 12; o++) {
        float b = bs[og * 12 + o];
        acc[o][0] = pack2(b, b);
        acc[o][1] = acc[o][0];
    }
    #pragma unroll 4
    for (int i = 0; i < 48; i++) {
        ulonglong2 v = *(const ulonglong2*)(h + base + (size_t)i * HW);
        #pragma unroll
        for (int o = 0; o < 12; o++) {
            unsigned long long w2 = ws2[i * 48 + og * 12 + o];
            acc[o][0] = ffma2(v.x, w2, acc[o][0]);
            acc[o][1] = ffma2(v.y, w2, acc[o][1]);
        }
    }
    __syncthreads();
    #pragma unroll
    for (int o = 0; o < 12; o++) {
        int oc = og * 12 + o;
        float4 r = *(const float4*)(h2 + base + (size_t)oc * HW);
        float a, b, c, d;
        unpack2(acc[o][0], a, b);
        unpack2(acc[o][1], c, d);
        a += r.x; b += r.y; c += r.z; d += r.w;
        if (do_gelu) { a = gelu_f(a); b = gelu_f(b); c = gelu_f(c); d = gelu_f(d); }
        *(float4*)(h + base + (size_t)oc * HW) = make_float4(a, b, c, d);
    }
}

// -------------------------- fused fc1+gelu+fc2 head --------------------------
__global__ void head_kernel(const float* __restrict__ h, const float* __restrict__ w1,
                            const float* __restrict__ b1, const float* __restrict__ w2,
                            const float* __restrict__ b2, float* __restrict__ out) {
    __shared__ unsigned long long w1s[1536];
    __shared__ float b1s[64];
    __shared__ float w2s[64];
    int tid = threadIdx.x;
    const unsigned long long* w1u = (const unsigned long long*)w1;
    for (int j = tid; j < 1536; j += 256) w1s[j] = w1u[j];
    if (tid < 64) { b1s[tid] = b1[tid]; w2s[tid] = w2[tid]; }
    __syncthreads();
    int q = blockIdx.x * 256 + tid;
    if (q >= 8 * 255 * 255) return;
    int c = q % 255;
    int t2 = q / 255;
    int r = t2 % 255;
    int bb = t2 / 255;
    size_t base = ((size_t)bb * CC) * HW + (size_t)r * 256 + c;
    unsigned long long acc[32];
    #pragma unroll
    for (int j = 0; j < 32; j++) acc[j] = pack2(b1s[2 * j], b1s[2 * j + 1]);
    #pragma unroll 4
    for (int i = 0; i < 48; i++) {
        float v = h[base + (size_t)i * HW];
        unsigned long long vv = pack2(v, v);
        #pragma unroll
        for (int j = 0; j < 32; j++) acc[j] = ffma2(vv, w1s[i * 32 + j], acc[j]);
    }
    float o = b2[0];
    #pragma unroll
    for (int j = 0; j < 32; j++) {
        float a, b;
        unpack2(acc[j], a, b);
        o += gelu_f(a) * w2s[2 * j] + gelu_f(b) * w2s[2 * j + 1];
    }
    out[q] = o;
}

// ---------------------------------- launch ----------------------------------
static inline int grd(long n, int bs) { return (int)((n + bs - 1) / bs); }

// smem sizes (bytes) matching template constexpr math
#define AFB1_SMEM ((7*278 + 2*63*134) * 4)        // 75320  (3 blocks/SM)
#define AFB2_SMEM ((5*156 + 2*59*72) * 4)         // 37104  (6 blocks/SM)
#define AFB3_SMEM ((53*94 + 2*53*42) * 4)         // 37736  (single chunk)
#define SFB3_SMEM ((4*24*42 + 2*36*42) * 4)       // 28224
#define SFB2_SMEM ((4*23*72 + 2*34*72) * 4)       // 46080
#define SFB1_SMEM ((4*22*134 + 2*32*134) * 4)     // 81472

extern "C" void kernel_launch(void* const* d_in, const int* in_sizes, int n_in,
                              void* d_out, int out_size) {
    const float* x     = (const float*)d_in[0];
    const float* fc0_w = (const float*)d_in[1];
    const float* fc0_b = (const float*)d_in[2];
    const float* wc[4] = { (const float*)d_in[3], (const float*)d_in[4],
                           (const float*)d_in[5], (const float*)d_in[6] };
    const float* cw    = (const float*)d_in[7];
    const float* cb    = (const float*)d_in[8];
    const float* fc1_w = (const float*)d_in[9];
    const float* fc1_b = (const float*)d_in[10];
    const float* fc2_w = (const float*)d_in[11];
    const float* fc2_b = (const float*)d_in[12];
    float* out = (float*)d_out;

    float *h, *h1, *h2, *ll1, *lh1, *hl1, *hh1, *ll2, *lh2, *hl2, *hh2, *b3;
    cudaGetSymbolAddress((void**)&h,   g_h);
    cudaGetSymbolAddress((void**)&h1,  g_h1);
    cudaGetSymbolAddress((void**)&h2,  g_h2);
    cudaGetSymbolAddress((void**)&ll1, g_ll1);
    cudaGetSymbolAddress((void**)&lh1, g_lh1);
    cudaGetSymbolAddress((void**)&hl1, g_hl1);
    cudaGetSymbolAddress((void**)&hh1, g_hh1);
    cudaGetSymbolAddress((void**)&ll2, g_ll2);
    cudaGetSymbolAddress((void**)&lh2, g_lh2);
    cudaGetSymbolAddress((void**)&hl2, g_hl2);
    cudaGetSymbolAddress((void**)&hh2, g_hh2);
    cudaGetSymbolAddress((void**)&b3,  g_b3);

    cudaFuncSetAttribute(afb2d<256,256,133,133,10,26,7,256>,
                         cudaFuncAttributeMaxDynamicSharedMemorySize, AFB1_SMEM);
    cudaFuncSetAttribute(sfb2d<133,133,32,512>,
                         cudaFuncAttributeMaxDynamicSharedMemorySize, SFB1_SMEM);

    fc0_kernel<<<grd((long)PP * HW, 256), 256>>>(x, fc0_w, fc0_b, h);

    for (int layer = 0; layer < 4; layer++) {
        // ---------------- forward DWT (3 fused levels) ----------------
        afb2d<256,256,133,133,10,26,7,256><<<dim3(6, PP), 256, AFB1_SMEM>>>(
            h, (long)HW, 256, ll1, lh1, hl1, hh1);
        afb2d<133,133,72,72,11,24,5,256><<<dim3(3, PP), 256, AFB2_SMEM>>>(
            ll1, 133L*133, 133, ll2, lh2, hl2, hh2);
        afb2d<72,72,41,41,10,21,53,256><<<dim3(2, PP), 256, AFB3_SMEM>>>(
            ll2, 72L*72, 72,
            b3 + 0L*B3SZ, b3 + 1L*B3SZ, b3 + 2L*B3SZ, b3 + 3L*B3SZ);

        // ---------------- coarsest-level channel mix ----------------
        mix_kernel<<<dim3(grd(PIX3,16), 4), 384>>>(b3, wc[layer], b3 + 4L*B3SZ);

        // ---------------- inverse DWT (3 fused levels) ----------------
        sfb2d<41,41,36,256><<<dim3(2, PP), 256, SFB3_SMEM>>>(
            b3 + 4L*B3SZ, (long)PIX3, 41,
            b3 + 5L*B3SZ, b3 + 6L*B3SZ, b3 + 7L*B3SZ, (long)PIX3, ll2);
        sfb2d<72,72,34,256><<<dim3(4, PP), 256, SFB2_SMEM>>>(
            ll2, 72L*72, 72, lh2, hl2, hh2, 72L*72, h1);
        sfb2d<133,133,32,512><<<dim3(8, PP), 512, SFB1_SMEM>>>(
            h1, 134L*134, 134, lh1, hl1, hh1, 133L*133, h2);

        // ---------------- pointwise conv + add + gelu ----------------
        pw_kernel<<<2048, 256>>>(h, h2, cw + (size_t)layer * 2304,
                                 cb + (size_t)layer * 48, layer < 3 ? 1 : 0);
    }

    head_kernel<<<grd(8L * 255 * 255, 256), 256>>>(h, fc1_w, fc1_b, fc2_w, fc2_b, out);
}

// round 14
// speedup vs baseline: 1.1770x; 1.0354x over previous
#include <cuda_runtime.h>
#include <math.h>

#define BB 8
#define CC 48
#define PP (BB*CC)          // 384 planes
#define N1 256
#define O1 133
#define O2 72
#define O3 41
#define HW (N1*N1)          // 65536
#define PIX3 (O3*O3)        // 1681
#define B3SZ (PP*PIX3)      // 645504

#define DLO_LIST { \
    -0.00107730108499558f, 0.004777257511010651f, 0.0005538422009938016f, \
    -0.031582039318031156f, 0.02752286553001629f, 0.09750160558707936f, \
    -0.12976686756709563f, -0.22626469396516913f, 0.3152503517092432f, \
    0.7511339080215775f, 0.4946238903983854f, 0.11154074335008017f }
#define DHI_LIST { \
    -0.11154074335008017f, 0.4946238903983854f, -0.7511339080215775f, \
    0.3152503517092432f, 0.22626469396516913f, -0.12976686756709563f, \
    -0.09750160558707936f, 0.02752286553001629f, 0.031582039318031156f, \
    0.0005538422009938016f, -0.004777257511010651f, -0.00107730108499558f }

// ------------------- scratch arena (static device memory) -------------------
__device__ float g_h  [PP*HW];
__device__ float g_h1 [PP*HW];      // 134x134 IDWT intermediate (L2 out)
__device__ float g_h2 [PP*HW];      // L1 synthesis output (pre-pointwise)
__device__ float g_ll1[PP*O1*O1];
__device__ float g_lh1[PP*O1*O1];
__device__ float g_hl1[PP*O1*O1];
__device__ float g_hh1[PP*O1*O1];
__device__ float g_ll2[PP*O2*O2];
__device__ float g_lh2[PP*O2*O2];
__device__ float g_hl2[PP*O2*O2];
__device__ float g_hh2[PP*O2*O2];
__device__ float g_b3 [8*B3SZ];

// --------------------------- f32x2 packed helpers ---------------------------
__device__ __forceinline__ unsigned long long pack2(float x, float y) {
    unsigned long long r;
    asm("mov.b64 %0, {%1, %2};" : "=l"(r) : "f"(x), "f"(y));
    return r;
}
__device__ __forceinline__ void unpack2(unsigned long long v, float &x, float &y) {
    asm("mov.b64 {%0, %1}, %2;" : "=f"(x), "=f"(y) : "l"(v));
}
__device__ __forceinline__ unsigned long long ffma2(unsigned long long a,
                                                    unsigned long long b,
                                                    unsigned long long c) {
    unsigned long long d;
    asm("fma.rn.f32x2 %0, %1, %2, %3;" : "=l"(d) : "l"(a), "l"(b), "l"(c));
    return d;
}

__device__ __forceinline__ float gelu_f(float x) {
    return 0.5f * x * (1.0f + erff(x * 0.7071067811865475f));
}

__device__ __forceinline__ int reflect1(int i, int n) {
    i = (i < 0)  ? -1 - i : i;
    i = (i >= n) ? 2 * n - 1 - i : i;
    return i;
}

// ------------------------------ fc0 + pad -----------------------------------
__global__ void fc0_kernel(const float* __restrict__ x,
                           const float* __restrict__ w,
                           const float* __restrict__ b,
                           float* __restrict__ out) {
    int idx = blockIdx.x * blockDim.x + threadIdx.x;
    if (idx >= PP * HW) return;
    int p  = idx & (HW - 1);
    int pc = idx >> 16;
    int ch = pc % CC, bb = pc / CC;
    int r = p >> 8, c = p & 255;
    float v = 0.f;
    if (r < 255 && c < 255) {
        const float* xp = x + (((size_t)bb * 255 + r) * 255 + c) * 4;
        v = b[ch];
        #pragma unroll
        for (int i = 0; i < 4; i++) v += xp[i] * w[i * CC + ch];
    }
    out[idx] = v;
}

// ---------------------- fused 2D analysis (row then col) --------------------
// VEC: interior staged via float4 (requires NC%4==0 and 16B-aligned rows).
template<int NR, int NC, int OR, int OC, int PADR, int K, int CH, int THREADS, bool VEC>
__global__ void __launch_bounds__(THREADS) afb2d(
    const float* __restrict__ in, long in_ps, int in_rs,
    float* __restrict__ ll, float* __restrict__ lh,
    float* __restrict__ hl, float* __restrict__ hh)
{
    constexpr int PW    = NC + 10 + PADR;
    constexpr int PWP   = (PW + 3) & ~1;
    constexpr int ROWS  = 2 * K + 11;
    constexpr int PITCH = (OC + 1) & ~1;
    constexpr int NPAIR = (OC + 1) / 2;
    constexpr long OPS  = (long)OR * OC;
    extern __shared__ float smem[];
    float* sIn = smem;                       // CH * PWP
    float* sLo = smem + CH * PWP;            // ROWS * PITCH
    float* sHi = sLo + ROWS * PITCH;         // ROWS * PITCH
    const float dlo[12] = DLO_LIST;
    const float dhi[12] = DHI_LIST;

    int p   = blockIdx.y;
    int k0  = blockIdx.x * K;
    int rbase = 2 * k0 - 10;
    int tid = threadIdx.x;
    const float* ip = in + (size_t)p * in_ps;

    for (int c0 = 0; c0 < ROWS; c0 += CH) {
        __syncthreads();
        if (VEC) {
            // interior: CH rows x NC/4 float4 loads (no reflection needed)
            constexpr int NC4 = NC / 4;
            for (int e = tid; e < CH * NC4; e += THREADS) {
                int j = e / NC4, c4 = e - j * NC4;
                int rr = reflect1(rbase + c0 + j, NR);
                float4 v = *(const float4*)(ip + (size_t)rr * in_rs + 4 * c4);
                float* d = sIn + j * PWP + 10 + 4 * c4;
                d[0] = v.x; d[1] = v.y; d[2] = v.z; d[3] = v.w;
            }
            // boundary: 10 left-pad + PADR right-pad columns per row
            constexpr int BW = 10 + PADR;
            for (int e = tid; e < CH * BW; e += THREADS) {
                int j = e / BW, c = e - j * BW;
                int col = (c < 10) ? c : (NC + c);   // padded-coord column
                int rr = reflect1(rbase + c0 + j, NR);
                int cc = reflect1(col - 10, NC);
                sIn[j * PWP + col] = ip[(size_t)rr * in_rs + cc];
            }
        } else {
            for (int e = tid; e < CH * PW; e += THREADS) {
                int j = e / PW, c = e - j * PW;
                int rr = reflect1(rbase + c0 + j, NR);
                int cc = reflect1(c - 10, NC);
                sIn[j * PWP + c] = ip[(size_t)rr * in_rs + cc];
            }
        }
        __syncthreads();
        for (int e = tid; e < CH * NPAIR; e += THREADS) {
            int j = e / NPAIR, t = e - j * NPAIR;
            int row = c0 + j;
            if (row < ROWS) {
                float v[14];
                const float2* sp = (const float2*)(sIn + j * PWP + 4 * t);
                #pragma unroll
                for (int m = 0; m < 7; m++) {
                    float2 q = sp[m];
                    v[2*m] = q.x; v[2*m+1] = q.y;
                }
                float ale = 0.f, ahe = 0.f, alo = 0.f, aho = 0.f;
                #pragma unroll
                for (int jj = 0; jj < 12; jj++) {
                    ale += v[jj]     * dlo[11 - jj];
                    ahe += v[jj]     * dhi[11 - jj];
                    alo += v[jj + 2] * dlo[11 - jj];
                    aho += v[jj + 2] * dhi[11 - jj];
                }
                sLo[row * PITCH + 2*t]     = ale;
                sHi[row * PITCH + 2*t]     = ahe;
                sLo[row * PITCH + 2*t + 1] = alo;
                sHi[row * PITCH + 2*t + 1] = aho;
            }
        }
    }
    __syncthreads();
    for (int e = tid; e < K * NPAIR; e += THREADS) {
        int k = e / NPAIR, cp = e - k * NPAIR;
        int kg = k0 + k;
        if (kg < OR) {
            int c = 2 * cp;
            float a0x=0,a0y=0,a1x=0,a1y=0,a2x=0,a2y=0,a3x=0,a3y=0;
            #pragma unroll
            for (int t = 0; t < 12; t++) {
                float2 a = *(const float2*)&sLo[(2*k + t) * PITCH + c];
                float2 b = *(const float2*)&sHi[(2*k + t) * PITCH + c];
                a0x += a.x * dlo[11-t]; a0y += a.y * dlo[11-t];
                a1x += a.x * dhi[11-t]; a1y += a.y * dhi[11-t];
                a2x += b.x * dlo[11-t]; a2y += b.y * dlo[11-t];
                a3x += b.x * dhi[11-t]; a3y += b.y * dhi[11-t];
            }
            size_t o = (size_t)p * OPS + (size_t)kg * OC + c;
            ll[o] = a0x; lh[o] = a1x; hl[o] = a2x; hh[o] = a3x;
            if (c + 1 < OC) {
                ll[o+1] = a0y; lh[o+1] = a1y; hl[o+1] = a2y; hh[o+1] = a3y;
            }
        }
    }
}

// ---------------------- fused 2D synthesis (col then row) -------------------
template<int NIN, int M, int KO, int THREADS>
__global__ void __launch_bounds__(THREADS) sfb2d(
    const float* __restrict__ bll, long ll_ps, int ll_rs,
    const float* __restrict__ blh, const float* __restrict__ bhl,
    const float* __restrict__ bhh, long b_ps,
    float* __restrict__ out)
{
    constexpr int W   = 2 * M - 10;
    constexpr int W2  = 2 * NIN - 10;
    constexpr int RIN = KO / 2 + 6;
    constexpr int MP  = (M + 1) & ~1;
    constexpr int CP  = (M + 1) / 2;
    constexpr int UP  = M - 5;
    extern __shared__ float smem[];
    float* s0 = smem;                  // RIN*MP each
    float* s1 = s0 + RIN * MP;
    float* s2 = s1 + RIN * MP;
    float* s3 = s2 + RIN * MP;
    float* sl = s3 + RIN * MP;         // KO*MP each
    float* sh = sl + KO * MP;
    const float dlo[12] = DLO_LIST;
    const float dhi[12] = DHI_LIST;

    int p  = blockIdx.y;
    int j0 = blockIdx.x * KO;
    int r0 = j0 >> 1;
    int tid = threadIdx.x;
    const float* pll = bll + (size_t)p * ll_ps;
    const float* plh = blh + (size_t)p * b_ps;
    const float* phl = bhl + (size_t)p * b_ps;
    const float* phh = bhh + (size_t)p * b_ps;

    for (int e = tid; e < RIN * M; e += THREADS) {
        int r = e / M, c = e - r * M;
        int rr = r0 + r; rr = (rr > NIN - 1) ? NIN - 1 : rr;
        int se = r * MP + c;
        s0[se] = pll[(size_t)rr * ll_rs + c];
        s1[se] = plh[(size_t)rr * M + c];
        s2[se] = phl[(size_t)rr * M + c];
        s3[se] = phh[(size_t)rr * M + c];
    }
    __syncthreads();
    for (int e = tid; e < (KO/2) * CP; e += THREADS) {
        int uj = e / CP, cp = e - uj * CP;
        int c = 2 * cp;
        float elx=0,ely=0,olx=0,oly=0,ehx=0,ehy=0,ohx=0,ohy=0;
        #pragma unroll
        for (int kk = 0; kk < 6; kk++) {
            int sb = (uj + kk) * MP + c;
            float2 a  = *(const float2*)&s0[sb];
            float2 b  = *(const float2*)&s1[sb];
            float2 g  = *(const float2*)&s2[sb];
            float2 hq = *(const float2*)&s3[sb];
            float ce = dlo[2*kk+1], co = dlo[2*kk];
            float de = dhi[2*kk+1], dq = dhi[2*kk];
            elx += a.x*ce + b.x*de;   ely += a.y*ce + b.y*de;
            olx += a.x*co + b.x*dq;   oly += a.y*co + b.y*dq;
            ehx += g.x*ce + hq.x*de;  ehy += g.y*ce + hq.y*de;
            ohx += g.x*co + hq.x*dq;  ohy += g.y*co + hq.y*dq;
        }
        int sb0 = (2*uj) * MP + c, sb1 = (2*uj + 1) * MP + c;
        sl[sb0] = elx; sl[sb1] = olx; sh[sb0] = ehx; sh[sb1] = ohx;
        if (c + 1 < M) {
            sl[sb0+1] = ely; sl[sb1+1] = oly; sh[sb0+1] = ehy; sh[sb1+1] = ohy;
        }
    }
    __syncthreads();
    for (int e = tid; e < KO * UP; e += THREADS) {
        int j = e / UP, u = e - j * UP;
        int jg = j0 + j;
        if (jg < W2) {
            float ev = 0.f, od = 0.f;
            #pragma unroll
            for (int kk = 0; kk < 6; kk++) {
                float a = sl[j * MP + u + kk], b = sh[j * MP + u + kk];
                ev += a * dlo[2*kk+1] + b * dhi[2*kk+1];
                od += a * dlo[2*kk]   + b * dhi[2*kk];
            }
            *(float2*)&out[((size_t)p * W2 + jg) * W + 2*u] = make_float2(ev, od);
        }
    }
}

// --------------------- per-pixel 48x48 channel mix (41x41) ------------------
__global__ void mix_kernel(const float* __restrict__ b3in, const float* __restrict__ w,
                           float* __restrict__ b3out) {
    __shared__ float ts[384 * 18];
    __shared__ float ws[4 * 48 * 18];
    int px0 = blockIdx.x * 16;
    int band = blockIdx.y;
    int tid = threadIdx.x;
    for (int e = tid; e < 384 * 16; e += 384) {
        int plane = e >> 4, px = e & 15;
        int gp = px0 + px;
        ts[plane * 18 + px] = (gp < PIX3)
            ? b3in[(size_t)band * B3SZ + (size_t)plane * PIX3 + gp] : 0.f;
    }
    int b = tid / 48, o = tid - b * 48;
    unsigned long long acc[8];
    #pragma unroll
    for (int m = 0; m < 8; m++) acc[m] = 0ull;
    const float* wband = w + (size_t)band * 2304 * PIX3;
    for (int ic = 0; ic < 12; ic++) {
        __syncthreads();
        for (int e = tid; e < 3072; e += 384) {
            int ii = e / 768;
            int rem = e - ii * 768;
            int oo = rem >> 4, px = rem & 15;
            int gp = px0 + px;
            ws[(ii * 48 + oo) * 18 + px] = (gp < PIX3)
                ? wband[((size_t)(ic * 4 + ii) * 48 + oo) * PIX3 + gp] : 0.f;
        }
        __syncthreads();
        #pragma unroll
        for (int i = 0; i < 4; i++) {
            const unsigned long long* tr =
                (const unsigned long long*)(ts + (b * 48 + ic * 4 + i) * 18);
            const unsigned long long* wr =
                (const unsigned long long*)(ws + (i * 48 + o) * 18);
            #pragma unroll
            for (int m = 0; m < 8; m++) acc[m] = ffma2(tr[m], wr[m], acc[m]);
        }
    }
    size_t obase = (size_t)band * B3SZ + (size_t)(b * 48 + o) * PIX3 + px0;
    #pragma unroll
    for (int m = 0; m < 8; m++) {
        float x, y;
        unpack2(acc[m], x, y);
        int gp0 = px0 + 2 * m;
        if (gp0 < PIX3)     b3out[obase + 2 * m]     = x;
        if (gp0 + 1 < PIX3) b3out[obase + 2 * m + 1] = y;
    }
}

// ------------------ pointwise conv + residual add + gelu --------------------
__global__ void pw_kernel(float* __restrict__ h, const float* __restrict__ h2,
                          const float* __restrict__ cw, const float* __restrict__ cb,
                          int do_gelu) {
    __shared__ unsigned long long ws2[2304];
    __shared__ float bs[48];
    int tid = threadIdx.x;
    for (int j = tid; j < 2304; j += 256) {
        int o = j / 48, i = j - o * 48;
        float w = cw[j];
        ws2[i * 48 + o] = pack2(w, w);
    }
    if (tid < 48) bs[tid] = cb[tid];
    __syncthreads();
    int og = tid >> 6;
    int pq = tid & 63;
    int bx = blockIdx.x;
    int bb = bx >> 8;
    int p0 = ((bx & 255) << 8) + (pq << 2);
    size_t base = ((size_t)bb * CC) * HW + p0;
    unsigned long long acc[12][2];
    #pragma unroll
    for (int o = 0; o < 12; o++) {
        float b = bs[og * 12 + o];
        acc[o][0] = pack2(b, b);
        acc[o][1] = acc[o][0];
    }
    #pragma unroll 4
    for (int i = 0; i < 48; i++) {
        ulonglong2 v = *(const ulonglong2*)(h + base + (size_t)i * HW);
        #pragma unroll
        for (int o = 0; o < 12; o++) {
            unsigned long long w2 = ws2[i * 48 + og * 12 + o];
            acc[o][0] = ffma2(v.x, w2, acc[o][0]);
            acc[o][1] = ffma2(v.y, w2, acc[o][1]);
        }
    }
    __syncthreads();
    #pragma unroll
    for (int o = 0; o < 12; o++) {
        int oc = og * 12 + o;
        float4 r = *(const float4*)(h2 + base + (size_t)oc * HW);
        float a, b, c, d;
        unpack2(acc[o][0], a, b);
        unpack2(acc[o][1], c, d);
        a += r.x; b += r.y; c += r.z; d += r.w;
        if (do_gelu) { a = gelu_f(a); b = gelu_f(b); c = gelu_f(c); d = gelu_f(d); }
        *(float4*)(h + base + (size_t)oc * HW) = make_float4(a, b, c, d);
    }
}

// -------------------------- fused fc1+gelu+fc2 head --------------------------
__global__ void head_kernel(const float* __restrict__ h, const float* __restrict__ w1,
                            const float* __restrict__ b1, const float* __restrict__ w2,
                            const float* __restrict__ b2, float* __restrict__ out) {
    __shared__ unsigned long long w1s[1536];
    __shared__ float b1s[64];
    __shared__ float w2s[64];
    int tid = threadIdx.x;
    const unsigned long long* w1u = (const unsigned long long*)w1;
    for (int j = tid; j < 1536; j += 256) w1s[j] = w1u[j];
    if (tid < 64) { b1s[tid] = b1[tid]; w2s[tid] = w2[tid]; }
    __syncthreads();
    int q = blockIdx.x * 256 + tid;
    if (q >= 8 * 255 * 255) return;
    int c = q % 255;
    int t2 = q / 255;
    int r = t2 % 255;
    int bb = t2 / 255;
    size_t base = ((size_t)bb * CC) * HW + (size_t)r * 256 + c;
    unsigned long long acc[32];
    #pragma unroll
    for (int j = 0; j < 32; j++) acc[j] = pack2(b1s[2 * j], b1s[2 * j + 1]);
    #pragma unroll 4
    for (int i = 0; i < 48; i++) {
        float v = h[base + (size_t)i * HW];
        unsigned long long vv = pack2(v, v);
        #pragma unroll
        for (int j = 0; j < 32; j++) acc[j] = ffma2(vv, w1s[i * 32 + j], acc[j]);
    }
    float o = b2[0];
    #pragma unroll
    for (int j = 0; j < 32; j++) {
        float a, b;
        unpack2(acc[j], a, b);
        o += gelu_f(a) * w2s[2 * j] + gelu_f(b) * w2s[2 * j + 1];
    }
    out[q] = o;
}

// ---------------------------------- launch ----------------------------------
static inline int grd(long n, int bs) { return (int)((n + bs - 1) / bs); }

// smem sizes (bytes) matching template constexpr math
#define AFB1_SMEM ((7*278 + 2*63*134) * 4)        // 75320  (3 blocks/SM)
#define AFB2_SMEM ((5*156 + 2*59*72) * 4)         // 37104  (6 blocks/SM)
#define AFB3_SMEM ((53*94 + 2*53*42) * 4)         // 37736  (single chunk)
#define SFB3_SMEM ((4*24*42 + 2*36*42) * 4)       // 28224
#define SFB2_SMEM ((4*23*72 + 2*34*72) * 4)       // 46080
#define SFB1_SMEM ((4*22*134 + 2*32*134) * 4)     // 81472

extern "C" void kernel_launch(void* const* d_in, const int* in_sizes, int n_in,
                              void* d_out, int out_size) {
    const float* x     = (const float*)d_in[0];
    const float* fc0_w = (const float*)d_in[1];
    const float* fc0_b = (const float*)d_in[2];
    const float* wc[4] = { (const float*)d_in[3], (const float*)d_in[4],
                           (const float*)d_in[5], (const float*)d_in[6] };
    const float* cw    = (const float*)d_in[7];
    const float* cb    = (const float*)d_in[8];
    const float* fc1_w = (const float*)d_in[9];
    const float* fc1_b = (const float*)d_in[10];
    const float* fc2_w = (const float*)d_in[11];
    const float* fc2_b = (const float*)d_in[12];
    float* out = (float*)d_out;

    float *h, *h1, *h2, *ll1, *lh1, *hl1, *hh1, *ll2, *lh2, *hl2, *hh2, *b3;
    cudaGetSymbolAddress((void**)&h,   g_h);
    cudaGetSymbolAddress((void**)&h1,  g_h1);
    cudaGetSymbolAddress((void**)&h2,  g_h2);
    cudaGetSymbolAddress((void**)&ll1, g_ll1);
    cudaGetSymbolAddress((void**)&lh1, g_lh1);
    cudaGetSymbolAddress((void**)&hl1, g_hl1);
    cudaGetSymbolAddress((void**)&hh1, g_hh1);
    cudaGetSymbolAddress((void**)&ll2, g_ll2);
    cudaGetSymbolAddress((void**)&lh2, g_lh2);
    cudaGetSymbolAddress((void**)&hl2, g_hl2);
    cudaGetSymbolAddress((void**)&hh2, g_hh2);
    cudaGetSymbolAddress((void**)&b3,  g_b3);

    cudaFuncSetAttribute(afb2d<256,256,133,133,10,26,7,256,true>,
                         cudaFuncAttributeMaxDynamicSharedMemorySize, AFB1_SMEM);
    cudaFuncSetAttribute(sfb2d<133,133,32,512>,
                         cudaFuncAttributeMaxDynamicSharedMemorySize, SFB1_SMEM);

    fc0_kernel<<<grd((long)PP * HW, 256), 256>>>(x, fc0_w, fc0_b, h);

    for (int layer = 0; layer < 4; layer++) {
        // ---------------- forward DWT (3 fused levels) ----------------
        afb2d<256,256,133,133,10,26,7,256,true><<<dim3(6, PP), 256, AFB1_SMEM>>>(
            h, (long)HW, 256, ll1, lh1, hl1, hh1);
        afb2d<133,133,72,72,11,24,5,256,false><<<dim3(3, PP), 256, AFB2_SMEM>>>(
            ll1, 133L*133, 133, ll2, lh2, hl2, hh2);
        afb2d<72,72,41,41,10,21,53,256,true><<<dim3(2, PP), 256, AFB3_SMEM>>>(
            ll2, 72L*72, 72,
            b3 + 0L*B3SZ, b3 + 1L*B3SZ, b3 + 2L*B3SZ, b3 + 3L*B3SZ);

        // ---------------- coarsest-level channel mix ----------------
        mix_kernel<<<dim3(grd(PIX3,16), 4), 384>>>(b3, wc[layer], b3 + 4L*B3SZ);

        // ---------------- inverse DWT (3 fused levels) ----------------
        sfb2d<41,41,36,256><<<dim3(2, PP), 256, SFB3_SMEM>>>(
            b3 + 4L*B3SZ, (long)PIX3, 41,
            b3 + 5L*B3SZ, b3 + 6L*B3SZ, b3 + 7L*B3SZ, (long)PIX3, ll2);
        sfb2d<72,72,34,256><<<dim3(4, PP), 256, SFB2_SMEM>>>(
            ll2, 72L*72, 72, lh2, hl2, hh2, 72L*72, h1);
        sfb2d<133,133,32,512><<<dim3(8, PP), 512, SFB1_SMEM>>>(
            h1, 134L*134, 134, lh1, hl1, hh1, 133L*133, h2);

        // ---------------- pointwise conv + add + gelu ----------------
        pw_kernel<<<2048, 256>>>(h, h2, cw + (size_t)layer * 2304,
                                 cb + (size_t)layer * 48, layer < 3 ? 1 : 0);
    }

    head_kernel<<<grd(8L * 255 * 255, 256), 256>>>(h, fc1_w, fc1_b, fc2_w, fc2_b, out);
}

// round 15
// speedup vs baseline: 1.1959x; 1.0160x over previous
#include <cuda_runtime.h>
#include <math.h>

#define BB 8
#define CC 48
#define PP (BB*CC)          // 384 planes
#define N1 256
#define O1 133
#define O2 72
#define O3 41
#define HW (N1*N1)          // 65536
#define PIX3 (O3*O3)        // 1681
#define B3SZ (PP*PIX3)      // 645504

#define DLO_LIST { \
    -0.00107730108499558f, 0.004777257511010651f, 0.0005538422009938016f, \
    -0.031582039318031156f, 0.02752286553001629f, 0.09750160558707936f, \
    -0.12976686756709563f, -0.22626469396516913f, 0.3152503517092432f, \
    0.7511339080215775f, 0.4946238903983854f, 0.11154074335008017f }
#define DHI_LIST { \
    -0.11154074335008017f, 0.4946238903983854f, -0.7511339080215775f, \
    0.3152503517092432f, 0.22626469396516913f, -0.12976686756709563f, \
    -0.09750160558707936f, 0.02752286553001629f, 0.031582039318031156f, \
    0.0005538422009938016f, -0.004777257511010651f, -0.00107730108499558f }

// ------------------- scratch arena (static device memory) -------------------
__device__ float g_h  [PP*HW];
__device__ float g_h1 [PP*HW];      // 134x134 IDWT intermediate (L2 out)
__device__ float g_h2 [PP*HW];      // L1 synthesis output (pre-pointwise)
__device__ float g_ll1[PP*O1*O1];
__device__ float g_lh1[PP*O1*O1];
__device__ float g_hl1[PP*O1*O1];
__device__ float g_hh1[PP*O1*O1];
__device__ float g_ll2[PP*O2*O2];
__device__ float g_lh2[PP*O2*O2];
__device__ float g_hl2[PP*O2*O2];
__device__ float g_hh2[PP*O2*O2];
__device__ float g_b3 [8*B3SZ];

// --------------------------- f32x2 packed helpers ---------------------------
__device__ __forceinline__ unsigned long long pack2(float x, float y) {
    unsigned long long r;
    asm("mov.b64 %0, {%1, %2};" : "=l"(r) : "f"(x), "f"(y));
    return r;
}
__device__ __forceinline__ void unpack2(unsigned long long v, float &x, float &y) {
    asm("mov.b64 {%0, %1}, %2;" : "=f"(x), "=f"(y) : "l"(v));
}
__device__ __forceinline__ unsigned long long ffma2(unsigned long long a,
                                                    unsigned long long b,
                                                    unsigned long long c) {
    unsigned long long d;
    asm("fma.rn.f32x2 %0, %1, %2, %3;" : "=l"(d) : "l"(a), "l"(b), "l"(c));
    return d;
}

__device__ __forceinline__ float gelu_f(float x) {
    return 0.5f * x * (1.0f + erff(x * 0.7071067811865475f));
}

__device__ __forceinline__ int reflect1(int i, int n) {
    i = (i < 0)  ? -1 - i : i;
    i = (i >= n) ? 2 * n - 1 - i : i;
    return i;
}

// ------------------------------ fc0 + pad -----------------------------------
// 4 consecutive pixels per thread; float4 x reads (16B-aligned) + float4 store.
__global__ void fc0_kernel(const float* __restrict__ x,
                           const float* __restrict__ w,
                           const float* __restrict__ b,
                           float* __restrict__ out) {
    int t4 = blockIdx.x * blockDim.x + threadIdx.x;
    if (t4 >= PP * HW / 4) return;
    int gidx = t4 << 2;
    int p  = gidx & (HW - 1);
    int pc = gidx >> 16;
    int ch = pc % CC, bb = pc / CC;
    int r = p >> 8, c = p & 255;       // c multiple of 4
    float4 o4 = make_float4(0.f, 0.f, 0.f, 0.f);
    if (r < 255) {
        float w0 = w[ch], w1 = w[CC + ch], w2 = w[2 * CC + ch], w3 = w[3 * CC + ch];
        float bv = b[ch];
        const float* xr = x + (((size_t)bb * 255 + r) * 255 + c) * 4;
        float vals[4];
        #pragma unroll
        for (int m = 0; m < 4; m++) {
            float v = 0.f;
            if (c + m < 255) {
                float4 xv = *(const float4*)(xr + 4 * m);
                v = bv + xv.x * w0 + xv.y * w1 + xv.z * w2 + xv.w * w3;
            }
            vals[m] = v;
        }
        o4 = make_float4(vals[0], vals[1], vals[2], vals[3]);
    }
    *(float4*)(out + gidx) = o4;
}

// ---------------------- fused 2D analysis (row then col) --------------------
// VEC: interior staged via float4 (requires NC%4==0 and 16B-aligned rows).
template<int NR, int NC, int OR, int OC, int PADR, int K, int CH, int THREADS, bool VEC>
__global__ void __launch_bounds__(THREADS) afb2d(
    const float* __restrict__ in, long in_ps, int in_rs,
    float* __restrict__ ll, float* __restrict__ lh,
    float* __restrict__ hl, float* __restrict__ hh)
{
    constexpr int PW    = NC + 10 + PADR;
    constexpr int PWP   = (PW + 3) & ~1;
    constexpr int ROWS  = 2 * K + 11;
    constexpr int PITCH = (OC + 1) & ~1;
    constexpr int NPAIR = (OC + 1) / 2;
    constexpr long OPS  = (long)OR * OC;
    extern __shared__ float smem[];
    float* sIn = smem;                       // CH * PWP
    float* sLo = smem + CH * PWP;            // ROWS * PITCH
    float* sHi = sLo + ROWS * PITCH;         // ROWS * PITCH
    const float dlo[12] = DLO_LIST;
    const float dhi[12] = DHI_LIST;

    int p   = blockIdx.y;
    int k0  = blockIdx.x * K;
    int rbase = 2 * k0 - 10;
    int tid = threadIdx.x;
    const float* ip = in + (size_t)p * in_ps;

    for (int c0 = 0; c0 < ROWS; c0 += CH) {
        __syncthreads();
        if (VEC) {
            constexpr int NC4 = NC / 4;
            for (int e = tid; e < CH * NC4; e += THREADS) {
                int j = e / NC4, c4 = e - j * NC4;
                int rr = reflect1(rbase + c0 + j, NR);
                float4 v = *(const float4*)(ip + (size_t)rr * in_rs + 4 * c4);
                float* d = sIn + j * PWP + 10 + 4 * c4;
                d[0] = v.x; d[1] = v.y; d[2] = v.z; d[3] = v.w;
            }
            constexpr int BW = 10 + PADR;
            for (int e = tid; e < CH * BW; e += THREADS) {
                int j = e / BW, c = e - j * BW;
                int col = (c < 10) ? c : (NC + c);
                int rr = reflect1(rbase + c0 + j, NR);
                int cc = reflect1(col - 10, NC);
                sIn[j * PWP + col] = ip[(size_t)rr * in_rs + cc];
            }
        } else {
            for (int e = tid; e < CH * PW; e += THREADS) {
                int j = e / PW, c = e - j * PW;
                int rr = reflect1(rbase + c0 + j, NR);
                int cc = reflect1(c - 10, NC);
                sIn[j * PWP + c] = ip[(size_t)rr * in_rs + cc];
            }
        }
        __syncthreads();
        for (int e = tid; e < CH * NPAIR; e += THREADS) {
            int j = e / NPAIR, t = e - j * NPAIR;
            int row = c0 + j;
            if (row < ROWS) {
                float v[14];
                const float2* sp = (const float2*)(sIn + j * PWP + 4 * t);
                #pragma unroll
                for (int m = 0; m < 7; m++) {
                    float2 q = sp[m];
                    v[2*m] = q.x; v[2*m+1] = q.y;
                }
                float ale = 0.f, ahe = 0.f, alo = 0.f, aho = 0.f;
                #pragma unroll
                for (int jj = 0; jj < 12; jj++) {
                    ale += v[jj]     * dlo[11 - jj];
                    ahe += v[jj]     * dhi[11 - jj];
                    alo += v[jj + 2] * dlo[11 - jj];
                    aho += v[jj + 2] * dhi[11 - jj];
                }
                sLo[row * PITCH + 2*t]     = ale;
                sHi[row * PITCH + 2*t]     = ahe;
                sLo[row * PITCH + 2*t + 1] = alo;
                sHi[row * PITCH + 2*t + 1] = aho;
            }
        }
    }
    __syncthreads();
    for (int e = tid; e < K * NPAIR; e += THREADS) {
        int k = e / NPAIR, cp = e - k * NPAIR;
        int kg = k0 + k;
        if (kg < OR) {
            int c = 2 * cp;
            float a0x=0,a0y=0,a1x=0,a1y=0,a2x=0,a2y=0,a3x=0,a3y=0;
            #pragma unroll
            for (int t = 0; t < 12; t++) {
                float2 a = *(const float2*)&sLo[(2*k + t) * PITCH + c];
                float2 b = *(const float2*)&sHi[(2*k + t) * PITCH + c];
                a0x += a.x * dlo[11-t]; a0y += a.y * dlo[11-t];
                a1x += a.x * dhi[11-t]; a1y += a.y * dhi[11-t];
                a2x += b.x * dlo[11-t]; a2y += b.y * dlo[11-t];
                a3x += b.x * dhi[11-t]; a3y += b.y * dhi[11-t];
            }
            size_t o = (size_t)p * OPS + (size_t)kg * OC + c;
            ll[o] = a0x; lh[o] = a1x; hl[o] = a2x; hh[o] = a3x;
            if (c + 1 < OC) {
                ll[o+1] = a0y; lh[o+1] = a1y; hl[o+1] = a2y; hh[o+1] = a3y;
            }
        }
    }
}

// ---------------------- fused 2D synthesis (col then row) -------------------
// VB: band staging via per-row float4 (requires M%4==0, MP==M, aligned rows,
//     ll contiguous with ll_rs==M).
template<int NIN, int M, int KO, int THREADS, bool VB>
__global__ void __launch_bounds__(THREADS) sfb2d(
    const float* __restrict__ bll, long ll_ps, int ll_rs,
    const float* __restrict__ blh, const float* __restrict__ bhl,
    const float* __restrict__ bhh, long b_ps,
    float* __restrict__ out)
{
    constexpr int W   = 2 * M - 10;
    constexpr int W2  = 2 * NIN - 10;
    constexpr int RIN = KO / 2 + 6;
    constexpr int MP  = (M + 1) & ~1;
    constexpr int CP  = (M + 1) / 2;
    constexpr int UP  = M - 5;
    extern __shared__ float smem[];
    float* s0 = smem;                  // RIN*MP each
    float* s1 = s0 + RIN * MP;
    float* s2 = s1 + RIN * MP;
    float* s3 = s2 + RIN * MP;
    float* sl = s3 + RIN * MP;         // KO*MP each
    float* sh = sl + KO * MP;
    const float dlo[12] = DLO_LIST;
    const float dhi[12] = DHI_LIST;

    int p  = blockIdx.y;
    int j0 = blockIdx.x * KO;
    int r0 = j0 >> 1;
    int tid = threadIdx.x;
    const float* pll = bll + (size_t)p * ll_ps;
    const float* plh = blh + (size_t)p * b_ps;
    const float* phl = bhl + (size_t)p * b_ps;
    const float* phh = bhh + (size_t)p * b_ps;

    if (VB) {
        constexpr int M4 = M / 4;
        for (int e = tid; e < RIN * M4; e += THREADS) {
            int r = e / M4, c4 = e - r * M4;
            int rr = r0 + r; rr = (rr > NIN - 1) ? NIN - 1 : rr;
            size_t go = (size_t)rr * M + 4 * c4;
            int se = r * MP + 4 * c4;
            float4 v;
            v = *(const float4*)(pll + go);
            s0[se] = v.x; s0[se+1] = v.y; s0[se+2] = v.z; s0[se+3] = v.w;
            v = *(const float4*)(plh + go);
            s1[se] = v.x; s1[se+1] = v.y; s1[se+2] = v.z; s1[se+3] = v.w;
            v = *(const float4*)(phl + go);
            s2[se] = v.x; s2[se+1] = v.y; s2[se+2] = v.z; s2[se+3] = v.w;
            v = *(const float4*)(phh + go);
            s3[se] = v.x; s3[se+1] = v.y; s3[se+2] = v.z; s3[se+3] = v.w;
        }
    } else {
        for (int e = tid; e < RIN * M; e += THREADS) {
            int r = e / M, c = e - r * M;
            int rr = r0 + r; rr = (rr > NIN - 1) ? NIN - 1 : rr;
            int se = r * MP + c;
            s0[se] = pll[(size_t)rr * ll_rs + c];
            s1[se] = plh[(size_t)rr * M + c];
            s2[se] = phl[(size_t)rr * M + c];
            s3[se] = phh[(size_t)rr * M + c];
        }
    }
    __syncthreads();
    for (int e = tid; e < (KO/2) * CP; e += THREADS) {
        int uj = e / CP, cp = e - uj * CP;
        int c = 2 * cp;
        float elx=0,ely=0,olx=0,oly=0,ehx=0,ehy=0,ohx=0,ohy=0;
        #pragma unroll
        for (int kk = 0; kk < 6; kk++) {
            int sb = (uj + kk) * MP + c;
            float2 a  = *(const float2*)&s0[sb];
            float2 b  = *(const float2*)&s1[sb];
            float2 g  = *(const float2*)&s2[sb];
            float2 hq = *(const float2*)&s3[sb];
            float ce = dlo[2*kk+1], co = dlo[2*kk];
            float de = dhi[2*kk+1], dq = dhi[2*kk];
            elx += a.x*ce + b.x*de;   ely += a.y*ce + b.y*de;
            olx += a.x*co + b.x*dq;   oly += a.y*co + b.y*dq;
            ehx += g.x*ce + hq.x*de;  ehy += g.y*ce + hq.y*de;
            ohx += g.x*co + hq.x*dq;  ohy += g.y*co + hq.y*dq;
        }
        int sb0 = (2*uj) * MP + c, sb1 = (2*uj + 1) * MP + c;
        sl[sb0] = elx; sl[sb1] = olx; sh[sb0] = ehx; sh[sb1] = ohx;
        if (c + 1 < M) {
            sl[sb0+1] = ely; sl[sb1+1] = oly; sh[sb0+1] = ehy; sh[sb1+1] = ohy;
        }
    }
    __syncthreads();
    for (int e = tid; e < KO * UP; e += THREADS) {
        int j = e / UP, u = e - j * UP;
        int jg = j0 + j;
        if (jg < W2) {
            float ev = 0.f, od = 0.f;
            #pragma unroll
            for (int kk = 0; kk < 6; kk++) {
                float a = sl[j * MP + u + kk], b = sh[j * MP + u + kk];
                ev += a * dlo[2*kk+1] + b * dhi[2*kk+1];
                od += a * dlo[2*kk]   + b * dhi[2*kk];
            }
            *(float2*)&out[((size_t)p * W2 + jg) * W + 2*u] = make_float2(ev, od);
        }
    }
}

// --------------------- per-pixel 48x48 channel mix (41x41) ------------------
__global__ void mix_kernel(const float* __restrict__ b3in, const float* __restrict__ w,
                           float* __restrict__ b3out) {
    __shared__ float ts[384 * 18];
    __shared__ float ws[4 * 48 * 18];
    int px0 = blockIdx.x * 16;
    int band = blockIdx.y;
    int tid = threadIdx.x;
    for (int e = tid; e < 384 * 16; e += 384) {
        int plane = e >> 4, px = e & 15;
        int gp = px0 + px;
        ts[plane * 18 + px] = (gp < PIX3)
            ? b3in[(size_t)band * B3SZ + (size_t)plane * PIX3 + gp] : 0.f;
    }
    int b = tid / 48, o = tid - b * 48;
    unsigned long long acc[8];
    #pragma unroll
    for (int m = 0; m < 8; m++) acc[m] = 0ull;
    const float* wband = w + (size_t)band * 2304 * PIX3;
    for (int ic = 0; ic < 12; ic++) {
        __syncthreads();
        for (int e = tid; e < 3072; e += 384) {
            int ii = e / 768;
            int rem = e - ii * 768;
            int oo = rem >> 4, px = rem & 15;
            int gp = px0 + px;
            ws[(ii * 48 + oo) * 18 + px] = (gp < PIX3)
                ? wband[((size_t)(ic * 4 + ii) * 48 + oo) * PIX3 + gp] : 0.f;
        }
        __syncthreads();
        #pragma unroll
        for (int i = 0; i < 4; i++) {
            const unsigned long long* tr =
                (const unsigned long long*)(ts + (b * 48 + ic * 4 + i) * 18);
            const unsigned long long* wr =
                (const unsigned long long*)(ws + (i * 48 + o) * 18);
            #pragma unroll
            for (int m = 0; m < 8; m++) acc[m] = ffma2(tr[m], wr[m], acc[m]);
        }
    }
    size_t obase = (size_t)band * B3SZ + (size_t)(b * 48 + o) * PIX3 + px0;
    #pragma unroll
    for (int m = 0; m < 8; m++) {
        float x, y;
        unpack2(acc[m], x, y);
        int gp0 = px0 + 2 * m;
        if (gp0 < PIX3)     b3out[obase + 2 * m]     = x;
        if (gp0 + 1 < PIX3) b3out[obase + 2 * m + 1] = y;
    }
}

// ------------------ pointwise conv + residual add + gelu --------------------
__global__ void pw_kernel(float* __restrict__ h, const float* __restrict__ h2,
                          const float* __restrict__ cw, const float* __restrict__ cb,
                          int do_gelu) {
    __shared__ unsigned long long ws2[2304];
    __shared__ float bs[48];
    int tid = threadIdx.x;
    for (int j = tid; j < 2304; j += 256) {
        int o = j / 48, i = j - o * 48;
        float w = cw[j];
        ws2[i * 48 + o] = pack2(w, w);
    }
    if (tid < 48) bs[tid] = cb[tid];
    __syncthreads();
    int og = tid >> 6;
    int pq = tid & 63;
    int bx = blockIdx.x;
    int bb = bx >> 8;
    int p0 = ((bx & 255) << 8) + (pq << 2);
    size_t base = ((size_t)bb * CC) * HW + p0;
    unsigned long long acc[12][2];
    #pragma unroll
    for (int o = 0; o < 12; o++) {
        float b = bs[og * 12 + o];
        acc[o][0] = pack2(b, b);
        acc[o][1] = acc[o][0];
    }
    #pragma unroll 4
    for (int i = 0; i < 48; i++) {
        ulonglong2 v = *(const ulonglong2*)(h + base + (size_t)i * HW);
        #pragma unroll
        for (int o = 0; o < 12; o++) {
            unsigned long long w2 = ws2[i * 48 + og * 12 + o];
            acc[o][0] = ffma2(v.x, w2, acc[o][0]);
            acc[o][1] = ffma2(v.y, w2, acc[o][1]);
        }
    }
    __syncthreads();
    #pragma unroll
    for (int o = 0; o < 12; o++) {
        int oc = og * 12 + o;
        float4 r = *(const float4*)(h2 + base + (size_t)oc * HW);
        float a, b, c, d;
        unpack2(acc[o][0], a, b);
        unpack2(acc[o][1], c, d);
        a += r.x; b += r.y; c += r.z; d += r.w;
        if (do_gelu) { a = gelu_f(a); b = gelu_f(b); c = gelu_f(c); d = gelu_f(d); }
        *(float4*)(h + base + (size_t)oc * HW) = make_float4(a, b, c, d);
    }
}

// -------------------------- fused fc1+gelu+fc2 head --------------------------
__global__ void head_kernel(const float* __restrict__ h, const float* __restrict__ w1,
                            const float* __restrict__ b1, const float* __restrict__ w2,
                            const float* __restrict__ b2, float* __restrict__ out) {
    __shared__ unsigned long long w1s[1536];
    __shared__ float b1s[64];
    __shared__ float w2s[64];
    int tid = threadIdx.x;
    const unsigned long long* w1u = (const unsigned long long*)w1;
    for (int j = tid; j < 1536; j += 256) w1s[j] = w1u[j];
    if (tid < 64) { b1s[tid] = b1[tid]; w2s[tid] = w2[tid]; }
    __syncthreads();
    int q = blockIdx.x * 256 + tid;
    if (q >= 8 * 255 * 255) return;
    int c = q % 255;
    int t2 = q / 255;
    int r = t2 % 255;
    int bb = t2 / 255;
    size_t base = ((size_t)bb * CC) * HW + (size_t)r * 256 + c;
    unsigned long long acc[32];
    #pragma unroll
    for (int j = 0; j < 32; j++) acc[j] = pack2(b1s[2 * j], b1s[2 * j + 1]);
    #pragma unroll 4
    for (int i = 0; i < 48; i++) {
        float v = h[base + (size_t)i * HW];
        unsigned long long vv = pack2(v, v);
        #pragma unroll
        for (int j = 0; j < 32; j++) acc[j] = ffma2(vv, w1s[i * 32 + j], acc[j]);
    }
    float o = b2[0];
    #pragma unroll
    for (int j = 0; j < 32; j++) {
        float a, b;
        unpack2(acc[j], a, b);
        o += gelu_f(a) * w2s[2 * j] + gelu_f(b) * w2s[2 * j + 1];
    }
    out[q] = o;
}

// ---------------------------------- launch ----------------------------------
static inline int grd(long n, int bs) { return (int)((n + bs - 1) / bs); }

// smem sizes (bytes) matching template constexpr math
#define AFB1_SMEM ((7*278 + 2*63*134) * 4)        // 75320  (3 blocks/SM)
#define AFB2_SMEM ((5*156 + 2*59*72) * 4)         // 37104  (6 blocks/SM)
#define AFB3_SMEM ((53*94 + 2*53*42) * 4)         // 37736  (single chunk)
#define SFB3_SMEM ((4*24*42 + 2*36*42) * 4)       // 28224
#define SFB2_SMEM ((4*23*72 + 2*34*72) * 4)       // 46080
#define SFB1_SMEM ((4*22*134 + 2*32*134) * 4)     // 81472

extern "C" void kernel_launch(void* const* d_in, const int* in_sizes, int n_in,
                              void* d_out, int out_size) {
    const float* x     = (const float*)d_in[0];
    const float* fc0_w = (const float*)d_in[1];
    const float* fc0_b = (const float*)d_in[2];
    const float* wc[4] = { (const float*)d_in[3], (const float*)d_in[4],
                           (const float*)d_in[5], (const float*)d_in[6] };
    const float* cw    = (const float*)d_in[7];
    const float* cb    = (const float*)d_in[8];
    const float* fc1_w = (const float*)d_in[9];
    const float* fc1_b = (const float*)d_in[10];
    const float* fc2_w = (const float*)d_in[11];
    const float* fc2_b = (const float*)d_in[12];
    float* out = (float*)d_out;

    float *h, *h1, *h2, *ll1, *lh1, *hl1, *hh1, *ll2, *lh2, *hl2, *hh2, *b3;
    cudaGetSymbolAddress((void**)&h,   g_h);
    cudaGetSymbolAddress((void**)&h1,  g_h1);
    cudaGetSymbolAddress((void**)&h2,  g_h2);
    cudaGetSymbolAddress((void**)&ll1, g_ll1);
    cudaGetSymbolAddress((void**)&lh1, g_lh1);
    cudaGetSymbolAddress((void**)&hl1, g_hl1);
    cudaGetSymbolAddress((void**)&hh1, g_hh1);
    cudaGetSymbolAddress((void**)&ll2, g_ll2);
    cudaGetSymbolAddress((void**)&lh2, g_lh2);
    cudaGetSymbolAddress((void**)&hl2, g_hl2);
    cudaGetSymbolAddress((void**)&hh2, g_hh2);
    cudaGetSymbolAddress((void**)&b3,  g_b3);

    cudaFuncSetAttribute(afb2d<256,256,133,133,10,26,7,256,true>,
                         cudaFuncAttributeMaxDynamicSharedMemorySize, AFB1_SMEM);
    cudaFuncSetAttribute(sfb2d<133,133,32,512,false>,
                         cudaFuncAttributeMaxDynamicSharedMemorySize, SFB1_SMEM);

    fc0_kernel<<<grd((long)PP * HW / 4, 256), 256>>>(x, fc0_w, fc0_b, h);

    for (int layer = 0; layer < 4; layer++) {
        // ---------------- forward DWT (3 fused levels) ----------------
        afb2d<256,256,133,133,10,26,7,256,true><<<dim3(6, PP), 256, AFB1_SMEM>>>(
            h, (long)HW, 256, ll1, lh1, hl1, hh1);
        afb2d<133,133,72,72,11,24,5,256,false><<<dim3(3, PP), 256, AFB2_SMEM>>>(
            ll1, 133L*133, 133, ll2, lh2, hl2, hh2);
        afb2d<72,72,41,41,10,21,53,256,true><<<dim3(2, PP), 256, AFB3_SMEM>>>(
            ll2, 72L*72, 72,
            b3 + 0L*B3SZ, b3 + 1L*B3SZ, b3 + 2L*B3SZ, b3 + 3L*B3SZ);

        // ---------------- coarsest-level channel mix ----------------
        mix_kernel<<<dim3(grd(PIX3,16), 4), 384>>>(b3, wc[layer], b3 + 4L*B3SZ);

        // ---------------- inverse DWT (3 fused levels) ----------------
        sfb2d<41,41,36,256,false><<<dim3(2, PP), 256, SFB3_SMEM>>>(
            b3 + 4L*B3SZ, (long)PIX3, 41,
            b3 + 5L*B3SZ, b3 + 6L*B3SZ, b3 + 7L*B3SZ, (long)PIX3, ll2);
        sfb2d<72,72,34,256,true><<<dim3(4, PP), 256, SFB2_SMEM>>>(
            ll2, 72L*72, 72, lh2, hl2, hh2, 72L*72, h1);
        sfb2d<133,133,32,512,false><<<dim3(8, PP), 512, SFB1_SMEM>>>(
            h1, 134L*134, 134, lh1, hl1, hh1, 133L*133, h2);

        // ---------------- pointwise conv + add + gelu ----------------
        pw_kernel<<<2048, 256>>>(h, h2, cw + (size_t)layer * 2304,
                                 cb + (size_t)layer * 48, layer < 3 ? 1 : 0);
    }

    head_kernel<<<grd(8L * 255 * 255, 256), 256>>>(h, fc1_w, fc1_b, fc2_w, fc2_b, out);
}

// round 16
// speedup vs baseline: 1.2009x; 1.0041x over previous
#include <cuda_runtime.h>
#include <math.h>

#define BB 8
#define CC 48
#define PP (BB*CC)          // 384 planes
#define N1 256
#define O1 133
#define O2 72
#define O3 41
#define HW (N1*N1)          // 65536
#define PIX3 (O3*O3)        // 1681
#define B3SZ (PP*PIX3)      // 645504

#define DLO_LIST { \
    -0.00107730108499558f, 0.004777257511010651f, 0.0005538422009938016f, \
    -0.031582039318031156f, 0.02752286553001629f, 0.09750160558707936f, \
    -0.12976686756709563f, -0.22626469396516913f, 0.3152503517092432f, \
    0.7511339080215775f, 0.4946238903983854f, 0.11154074335008017f }
#define DHI_LIST { \
    -0.11154074335008017f, 0.4946238903983854f, -0.7511339080215775f, \
    0.3152503517092432f, 0.22626469396516913f, -0.12976686756709563f, \
    -0.09750160558707936f, 0.02752286553001629f, 0.031582039318031156f, \
    0.0005538422009938016f, -0.004777257511010651f, -0.00107730108499558f }

// ------------------- scratch arena (static device memory) -------------------
__device__ float g_h  [PP*HW];
__device__ float g_h1 [PP*HW];      // 134x134 IDWT intermediate (L2 out)
__device__ float g_h2 [PP*HW];      // L1 synthesis output (pre-pointwise)
__device__ float g_ll1[PP*O1*O1];
__device__ float g_lh1[PP*O1*O1];
__device__ float g_hl1[PP*O1*O1];
__device__ float g_hh1[PP*O1*O1];
__device__ float g_ll2[PP*O2*O2];
__device__ float g_lh2[PP*O2*O2];
__device__ float g_hl2[PP*O2*O2];
__device__ float g_hh2[PP*O2*O2];
__device__ float g_b3 [8*B3SZ];

// --------------------------- f32x2 packed helpers ---------------------------
__device__ __forceinline__ unsigned long long pack2(float x, float y) {
    unsigned long long r;
    asm("mov.b64 %0, {%1, %2};" : "=l"(r) : "f"(x), "f"(y));
    return r;
}
__device__ __forceinline__ void unpack2(unsigned long long v, float &x, float &y) {
    asm("mov.b64 {%0, %1}, %2;" : "=f"(x), "=f"(y) : "l"(v));
}
__device__ __forceinline__ unsigned long long ffma2(unsigned long long a,
                                                    unsigned long long b,
                                                    unsigned long long c) {
    unsigned long long d;
    asm("fma.rn.f32x2 %0, %1, %2, %3;" : "=l"(d) : "l"(a), "l"(b), "l"(c));
    return d;
}

__device__ __forceinline__ float gelu_f(float x) {
    return 0.5f * x * (1.0f + erff(x * 0.7071067811865475f));
}

__device__ __forceinline__ int reflect1(int i, int n) {
    i = (i < 0)  ? -1 - i : i;
    i = (i >= n) ? 2 * n - 1 - i : i;
    return i;
}

// ------------------------------ fc0 + pad -----------------------------------
// 4 consecutive pixels per thread; float4 x reads (16B-aligned) + float4 store.
__global__ void fc0_kernel(const float* __restrict__ x,
                           const float* __restrict__ w,
                           const float* __restrict__ b,
                           float* __restrict__ out) {
    int t4 = blockIdx.x * blockDim.x + threadIdx.x;
    if (t4 >= PP * HW / 4) return;
    int gidx = t4 << 2;
    int p  = gidx & (HW - 1);
    int pc = gidx >> 16;
    int ch = pc % CC, bb = pc / CC;
    int r = p >> 8, c = p & 255;       // c multiple of 4
    float4 o4 = make_float4(0.f, 0.f, 0.f, 0.f);
    if (r < 255) {
        float w0 = w[ch], w1 = w[CC + ch], w2 = w[2 * CC + ch], w3 = w[3 * CC + ch];
        float bv = b[ch];
        const float* xr = x + (((size_t)bb * 255 + r) * 255 + c) * 4;
        float vals[4];
        #pragma unroll
        for (int m = 0; m < 4; m++) {
            float v = 0.f;
            if (c + m < 255) {
                float4 xv = *(const float4*)(xr + 4 * m);
                v = bv + xv.x * w0 + xv.y * w1 + xv.z * w2 + xv.w * w3;
            }
            vals[m] = v;
        }
        o4 = make_float4(vals[0], vals[1], vals[2], vals[3]);
    }
    *(float4*)(out + gidx) = o4;
}

// ---------------------- fused 2D analysis (row then col) --------------------
// VEC: interior staged via float4 (requires NC%4==0 and 16B-aligned rows).
template<int NR, int NC, int OR, int OC, int PADR, int K, int CH, int THREADS, bool VEC>
__global__ void __launch_bounds__(THREADS) afb2d(
    const float* __restrict__ in, long in_ps, int in_rs,
    float* __restrict__ ll, float* __restrict__ lh,
    float* __restrict__ hl, float* __restrict__ hh)
{
    constexpr int PW    = NC + 10 + PADR;
    constexpr int PWP   = (PW + 3) & ~1;
    constexpr int ROWS  = 2 * K + 11;
    constexpr int PITCH = (OC + 1) & ~1;
    constexpr int NPAIR = (OC + 1) / 2;
    constexpr long OPS  = (long)OR * OC;
    extern __shared__ float smem[];
    float* sIn = smem;                       // CH * PWP
    float* sLo = smem + CH * PWP;            // ROWS * PITCH
    float* sHi = sLo + ROWS * PITCH;         // ROWS * PITCH
    const float dlo[12] = DLO_LIST;
    const float dhi[12] = DHI_LIST;

    int p   = blockIdx.y;
    int k0  = blockIdx.x * K;
    int rbase = 2 * k0 - 10;
    int tid = threadIdx.x;
    const float* ip = in + (size_t)p * in_ps;

    for (int c0 = 0; c0 < ROWS; c0 += CH) {
        __syncthreads();
        if (VEC) {
            constexpr int NC4 = NC / 4;
            for (int e = tid; e < CH * NC4; e += THREADS) {
                int j = e / NC4, c4 = e - j * NC4;
                int rr = reflect1(rbase + c0 + j, NR);
                float4 v = *(const float4*)(ip + (size_t)rr * in_rs + 4 * c4);
                float* d = sIn + j * PWP + 10 + 4 * c4;
                d[0] = v.x; d[1] = v.y; d[2] = v.z; d[3] = v.w;
            }
            constexpr int BW = 10 + PADR;
            for (int e = tid; e < CH * BW; e += THREADS) {
                int j = e / BW, c = e - j * BW;
                int col = (c < 10) ? c : (NC + c);
                int rr = reflect1(rbase + c0 + j, NR);
                int cc = reflect1(col - 10, NC);
                sIn[j * PWP + col] = ip[(size_t)rr * in_rs + cc];
            }
        } else {
            for (int e = tid; e < CH * PW; e += THREADS) {
                int j = e / PW, c = e - j * PW;
                int rr = reflect1(rbase + c0 + j, NR);
                int cc = reflect1(c - 10, NC);
                sIn[j * PWP + c] = ip[(size_t)rr * in_rs + cc];
            }
        }
        __syncthreads();
        for (int e = tid; e < CH * NPAIR; e += THREADS) {
            int j = e / NPAIR, t = e - j * NPAIR;
            int row = c0 + j;
            if (row < ROWS) {
                float v[14];
                const float2* sp = (const float2*)(sIn + j * PWP + 4 * t);
                #pragma unroll
                for (int m = 0; m < 7; m++) {
                    float2 q = sp[m];
                    v[2*m] = q.x; v[2*m+1] = q.y;
                }
                float ale = 0.f, ahe = 0.f, alo = 0.f, aho = 0.f;
                #pragma unroll
                for (int jj = 0; jj < 12; jj++) {
                    ale += v[jj]     * dlo[11 - jj];
                    ahe += v[jj]     * dhi[11 - jj];
                    alo += v[jj + 2] * dlo[11 - jj];
                    aho += v[jj + 2] * dhi[11 - jj];
                }
                // paired 8B smem stores (PITCH even, 2t even -> aligned)
                *(float2*)&sLo[row * PITCH + 2*t] = make_float2(ale, alo);
                *(float2*)&sHi[row * PITCH + 2*t] = make_float2(ahe, aho);
            }
        }
    }
    __syncthreads();
    for (int e = tid; e < K * NPAIR; e += THREADS) {
        int k = e / NPAIR, cp = e - k * NPAIR;
        int kg = k0 + k;
        if (kg < OR) {
            int c = 2 * cp;
            float a0x=0,a0y=0,a1x=0,a1y=0,a2x=0,a2y=0,a3x=0,a3y=0;
            #pragma unroll
            for (int t = 0; t < 12; t++) {
                float2 a = *(const float2*)&sLo[(2*k + t) * PITCH + c];
                float2 b = *(const float2*)&sHi[(2*k + t) * PITCH + c];
                a0x += a.x * dlo[11-t]; a0y += a.y * dlo[11-t];
                a1x += a.x * dhi[11-t]; a1y += a.y * dhi[11-t];
                a2x += b.x * dlo[11-t]; a2y += b.y * dlo[11-t];
                a3x += b.x * dhi[11-t]; a3y += b.y * dhi[11-t];
            }
            size_t o = (size_t)p * OPS + (size_t)kg * OC + c;
            ll[o] = a0x; lh[o] = a1x; hl[o] = a2x; hh[o] = a3x;
            if (c + 1 < OC) {
                ll[o+1] = a0y; lh[o+1] = a1y; hl[o+1] = a2y; hh[o+1] = a3y;
            }
        }
    }
}

// ---------------------- fused 2D synthesis (col then row) -------------------
// VB: band staging via per-row float4 (requires M%4==0, MP==M, aligned rows,
//     ll contiguous with ll_rs==M).
template<int NIN, int M, int KO, int THREADS, bool VB>
__global__ void __launch_bounds__(THREADS) sfb2d(
    const float* __restrict__ bll, long ll_ps, int ll_rs,
    const float* __restrict__ blh, const float* __restrict__ bhl,
    const float* __restrict__ bhh, long b_ps,
    float* __restrict__ out)
{
    constexpr int W   = 2 * M - 10;
    constexpr int W2  = 2 * NIN - 10;
    constexpr int RIN = KO / 2 + 6;
    constexpr int MP  = (M + 1) & ~1;
    constexpr int CP  = (M + 1) / 2;
    constexpr int UP  = M - 5;
    extern __shared__ float smem[];
    float* s0 = smem;                  // RIN*MP each
    float* s1 = s0 + RIN * MP;
    float* s2 = s1 + RIN * MP;
    float* s3 = s2 + RIN * MP;
    float* sl = s3 + RIN * MP;         // KO*MP each
    float* sh = sl + KO * MP;
    const float dlo[12] = DLO_LIST;
    const float dhi[12] = DHI_LIST;

    int p  = blockIdx.y;
    int j0 = blockIdx.x * KO;
    int r0 = j0 >> 1;
    int tid = threadIdx.x;
    const float* pll = bll + (size_t)p * ll_ps;
    const float* plh = blh + (size_t)p * b_ps;
    const float* phl = bhl + (size_t)p * b_ps;
    const float* phh = bhh + (size_t)p * b_ps;

    if (VB) {
        constexpr int M4 = M / 4;
        for (int e = tid; e < RIN * M4; e += THREADS) {
            int r = e / M4, c4 = e - r * M4;
            int rr = r0 + r; rr = (rr > NIN - 1) ? NIN - 1 : rr;
            size_t go = (size_t)rr * M + 4 * c4;
            int se = r * MP + 4 * c4;
            float4 v;
            v = *(const float4*)(pll + go);
            s0[se] = v.x; s0[se+1] = v.y; s0[se+2] = v.z; s0[se+3] = v.w;
            v = *(const float4*)(plh + go);
            s1[se] = v.x; s1[se+1] = v.y; s1[se+2] = v.z; s1[se+3] = v.w;
            v = *(const float4*)(phl + go);
            s2[se] = v.x; s2[se+1] = v.y; s2[se+2] = v.z; s2[se+3] = v.w;
            v = *(const float4*)(phh + go);
            s3[se] = v.x; s3[se+1] = v.y; s3[se+2] = v.z; s3[se+3] = v.w;
        }
    } else {
        for (int e = tid; e < RIN * M; e += THREADS) {
            int r = e / M, c = e - r * M;
            int rr = r0 + r; rr = (rr > NIN - 1) ? NIN - 1 : rr;
            int se = r * MP + c;
            s0[se] = pll[(size_t)rr * ll_rs + c];
            s1[se] = plh[(size_t)rr * M + c];
            s2[se] = phl[(size_t)rr * M + c];
            s3[se] = phh[(size_t)rr * M + c];
        }
    }
    __syncthreads();
    for (int e = tid; e < (KO/2) * CP; e += THREADS) {
        int uj = e / CP, cp = e - uj * CP;
        int c = 2 * cp;
        float elx=0,ely=0,olx=0,oly=0,ehx=0,ehy=0,ohx=0,ohy=0;
        #pragma unroll
        for (int kk = 0; kk < 6; kk++) {
            int sb = (uj + kk) * MP + c;
            float2 a  = *(const float2*)&s0[sb];
            float2 b  = *(const float2*)&s1[sb];
            float2 g  = *(const float2*)&s2[sb];
            float2 hq = *(const float2*)&s3[sb];
            float ce = dlo[2*kk+1], co = dlo[2*kk];
            float de = dhi[2*kk+1], dq = dhi[2*kk];
            elx += a.x*ce + b.x*de;   ely += a.y*ce + b.y*de;
            olx += a.x*co + b.x*dq;   oly += a.y*co + b.y*dq;
            ehx += g.x*ce + hq.x*de;  ehy += g.y*ce + hq.y*de;
            ohx += g.x*co + hq.x*dq;  ohy += g.y*co + hq.y*dq;
        }
        int sb0 = (2*uj) * MP + c, sb1 = (2*uj + 1) * MP + c;
        if (c + 1 < M) {
            // paired 8B smem stores (c even, MP even -> aligned)
            *(float2*)&sl[sb0] = make_float2(elx, ely);
            *(float2*)&sl[sb1] = make_float2(olx, oly);
            *(float2*)&sh[sb0] = make_float2(ehx, ehy);
            *(float2*)&sh[sb1] = make_float2(ohx, ohy);
        } else {
            sl[sb0] = elx; sl[sb1] = olx; sh[sb0] = ehx; sh[sb1] = ohx;
        }
    }
    __syncthreads();
    for (int e = tid; e < KO * UP; e += THREADS) {
        int j = e / UP, u = e - j * UP;
        int jg = j0 + j;
        if (jg < W2) {
            float ev = 0.f, od = 0.f;
            #pragma unroll
            for (int kk = 0; kk < 6; kk++) {
                float a = sl[j * MP + u + kk], b = sh[j * MP + u + kk];
                ev += a * dlo[2*kk+1] + b * dhi[2*kk+1];
                od += a * dlo[2*kk]   + b * dhi[2*kk];
            }
            *(float2*)&out[((size_t)p * W2 + jg) * W + 2*u] = make_float2(ev, od);
        }
    }
}

// --------------------- per-pixel 48x48 channel mix (41x41) ------------------
__global__ void mix_kernel(const float* __restrict__ b3in, const float* __restrict__ w,
                           float* __restrict__ b3out) {
    __shared__ float ts[384 * 18];
    __shared__ float ws[4 * 48 * 18];
    int px0 = blockIdx.x * 16;
    int band = blockIdx.y;
    int tid = threadIdx.x;
    for (int e = tid; e < 384 * 16; e += 384) {
        int plane = e >> 4, px = e & 15;
        int gp = px0 + px;
        ts[plane * 18 + px] = (gp < PIX3)
            ? b3in[(size_t)band * B3SZ + (size_t)plane * PIX3 + gp] : 0.f;
    }
    int b = tid / 48, o = tid - b * 48;
    unsigned long long acc[8];
    #pragma unroll
    for (int m = 0; m < 8; m++) acc[m] = 0ull;
    const float* wband = w + (size_t)band * 2304 * PIX3;
    for (int ic = 0; ic < 12; ic++) {
        __syncthreads();
        for (int e = tid; e < 3072; e += 384) {
            int ii = e / 768;
            int rem = e - ii * 768;
            int oo = rem >> 4, px = rem & 15;
            int gp = px0 + px;
            ws[(ii * 48 + oo) * 18 + px] = (gp < PIX3)
                ? wband[((size_t)(ic * 4 + ii) * 48 + oo) * PIX3 + gp] : 0.f;
        }
        __syncthreads();
        #pragma unroll
        for (int i = 0; i < 4; i++) {
            const unsigned long long* tr =
                (const unsigned long long*)(ts + (b * 48 + ic * 4 + i) * 18);
            const unsigned long long* wr =
                (const unsigned long long*)(ws + (i * 48 + o) * 18);
            #pragma unroll
            for (int m = 0; m < 8; m++) acc[m] = ffma2(tr[m], wr[m], acc[m]);
        }
    }
    size_t obase = (size_t)band * B3SZ + (size_t)(b * 48 + o) * PIX3 + px0;
    #pragma unroll
    for (int m = 0; m < 8; m++) {
        float x, y;
        unpack2(acc[m], x, y);
        int gp0 = px0 + 2 * m;
        if (gp0 < PIX3)     b3out[obase + 2 * m]     = x;
        if (gp0 + 1 < PIX3) b3out[obase + 2 * m + 1] = y;
    }
}

// ------------------ pointwise conv + residual add + gelu --------------------
__global__ void pw_kernel(float* __restrict__ h, const float* __restrict__ h2,
                          const float* __restrict__ cw, const float* __restrict__ cb,
                          int do_gelu) {
    __shared__ unsigned long long ws2[2304];
    __shared__ float bs[48];
    int tid = threadIdx.x;
    for (int j = tid; j < 2304; j += 256) {
        int o = j / 48, i = j - o * 48;
        float w = cw[j];
        ws2[i * 48 + o] = pack2(w, w);
    }
    if (tid < 48) bs[tid] = cb[tid];
    __syncthreads();
    int og = tid >> 6;
    int pq = tid & 63;
    int bx = blockIdx.x;
    int bb = bx >> 8;
    int p0 = ((bx & 255) << 8) + (pq << 2);
    size_t base = ((size_t)bb * CC) * HW + p0;
    unsigned long long acc[12][2];
    #pragma unroll
    for (int o = 0; o < 12; o++) {
        float b = bs[og * 12 + o];
        acc[o][0] = pack2(b, b);
        acc[o][1] = acc[o][0];
    }
    #pragma unroll 4
    for (int i = 0; i < 48; i++) {
        ulonglong2 v = *(const ulonglong2*)(h + base + (size_t)i * HW);
        #pragma unroll
        for (int o = 0; o < 12; o++) {
            unsigned long long w2 = ws2[i * 48 + og * 12 + o];
            acc[o][0] = ffma2(v.x, w2, acc[o][0]);
            acc[o][1] = ffma2(v.y, w2, acc[o][1]);
        }
    }
    __syncthreads();
    #pragma unroll
    for (int o = 0; o < 12; o++) {
        int oc = og * 12 + o;
        float4 r = *(const float4*)(h2 + base + (size_t)oc * HW);
        float a, b, c, d;
        unpack2(acc[o][0], a, b);
        unpack2(acc[o][1], c, d);
        a += r.x; b += r.y; c += r.z; d += r.w;
        if (do_gelu) { a = gelu_f(a); b = gelu_f(b); c = gelu_f(c); d = gelu_f(d); }
        *(float4*)(h + base + (size_t)oc * HW) = make_float4(a, b, c, d);
    }
}

// -------------------------- fused fc1+gelu+fc2 head --------------------------
__global__ void head_kernel(const float* __restrict__ h, const float* __restrict__ w1,
                            const float* __restrict__ b1, const float* __restrict__ w2,
                            const float* __restrict__ b2, float* __restrict__ out) {
    __shared__ unsigned long long w1s[1536];
    __shared__ float b1s[64];
    __shared__ float w2s[64];
    int tid = threadIdx.x;
    const unsigned long long* w1u = (const unsigned long long*)w1;
    for (int j = tid; j < 1536; j += 256) w1s[j] = w1u[j];
    if (tid < 64) { b1s[tid] = b1[tid]; w2s[tid] = w2[tid]; }
    __syncthreads();
    int q = blockIdx.x * 256 + tid;
    if (q >= 8 * 255 * 255) return;
    int c = q % 255;
    int t2 = q / 255;
    int r = t2 % 255;
    int bb = t2 / 255;
    size_t base = ((size_t)bb * CC) * HW + (size_t)r * 256 + c;
    unsigned long long acc[32];
    #pragma unroll
    for (int j = 0; j < 32; j++) acc[j] = pack2(b1s[2 * j], b1s[2 * j + 1]);
    #pragma unroll 4
    for (int i = 0; i < 48; i++) {
        float v = h[base + (size_t)i * HW];
        unsigned long long vv = pack2(v, v);
        #pragma unroll
        for (int j = 0; j < 32; j++) acc[j] = ffma2(vv, w1s[i * 32 + j], acc[j]);
    }
    float o = b2[0];
    #pragma unroll
    for (int j = 0; j < 32; j++) {
        float a, b;
        unpack2(acc[j], a, b);
        o += gelu_f(a) * w2s[2 * j] + gelu_f(b) * w2s[2 * j + 1];
    }
    out[q] = o;
}

// ---------------------------------- launch ----------------------------------
static inline int grd(long n, int bs) { return (int)((n + bs - 1) / bs); }

// smem sizes (bytes) matching template constexpr math
#define AFB1_SMEM ((7*278 + 2*63*134) * 4)        // 75320  (3 blocks/SM)
#define AFB2_SMEM ((5*156 + 2*59*72) * 4)         // 37104  (6 blocks/SM)
#define AFB3_SMEM ((53*94 + 2*53*42) * 4)         // 37736  (single chunk)
#define SFB3_SMEM ((4*24*42 + 2*36*42) * 4)       // 28224
#define SFB2_SMEM ((4*23*72 + 2*34*72) * 4)       // 46080
#define SFB1_SMEM ((4*22*134 + 2*32*134) * 4)     // 81472

extern "C" void kernel_launch(void* const* d_in, const int* in_sizes, int n_in,
                              void* d_out, int out_size) {
    const float* x     = (const float*)d_in[0];
    const float* fc0_w = (const float*)d_in[1];
    const float* fc0_b = (const float*)d_in[2];
    const float* wc[4] = { (const float*)d_in[3], (const float*)d_in[4],
                           (const float*)d_in[5], (const float*)d_in[6] };
    const float* cw    = (const float*)d_in[7];
    const float* cb    = (const float*)d_in[8];
    const float* fc1_w = (const float*)d_in[9];
    const float* fc1_b = (const float*)d_in[10];
    const float* fc2_w = (const float*)d_in[11];
    const float* fc2_b = (const float*)d_in[12];
    float* out = (float*)d_out;

    float *h, *h1, *h2, *ll1, *lh1, *hl1, *hh1, *ll2, *lh2, *hl2, *hh2, *b3;
    cudaGetSymbolAddress((void**)&h,   g_h);
    cudaGetSymbolAddress((void**)&h1,  g_h1);
    cudaGetSymbolAddress((void**)&h2,  g_h2);
    cudaGetSymbolAddress((void**)&ll1, g_ll1);
    cudaGetSymbolAddress((void**)&lh1, g_lh1);
    cudaGetSymbolAddress((void**)&hl1, g_hl1);
    cudaGetSymbolAddress((void**)&hh1, g_hh1);
    cudaGetSymbolAddress((void**)&ll2, g_ll2);
    cudaGetSymbolAddress((void**)&lh2, g_lh2);
    cudaGetSymbolAddress((void**)&hl2, g_hl2);
    cudaGetSymbolAddress((void**)&hh2, g_hh2);
    cudaGetSymbolAddress((void**)&b3,  g_b3);

    cudaFuncSetAttribute(afb2d<256,256,133,133,10,26,7,256,true>,
                         cudaFuncAttributeMaxDynamicSharedMemorySize, AFB1_SMEM);
    cudaFuncSetAttribute(sfb2d<133,133,32,512,false>,
                         cudaFuncAttributeMaxDynamicSharedMemorySize, SFB1_SMEM);

    fc0_kernel<<<grd((long)PP * HW / 4, 256), 256>>>(x, fc0_w, fc0_b, h);

    for (int layer = 0; layer < 4; layer++) {
        // ---------------- forward DWT (3 fused levels) ----------------
        afb2d<256,256,133,133,10,26,7,256,true><<<dim3(6, PP), 256, AFB1_SMEM>>>(
            h, (long)HW, 256, ll1, lh1, hl1, hh1);
        afb2d<133,133,72,72,11,24,5,256,false><<<dim3(3, PP), 256, AFB2_SMEM>>>(
            ll1, 133L*133, 133, ll2, lh2, hl2, hh2);
        afb2d<72,72,41,41,10,21,53,256,true><<<dim3(2, PP), 256, AFB3_SMEM>>>(
            ll2, 72L*72, 72,
            b3 + 0L*B3SZ, b3 + 1L*B3SZ, b3 + 2L*B3SZ, b3 + 3L*B3SZ);

        // ---------------- coarsest-level channel mix ----------------
        mix_kernel<<<dim3(grd(PIX3,16), 4), 384>>>(b3, wc[layer], b3 + 4L*B3SZ);

        // ---------------- inverse DWT (3 fused levels) ----------------
        sfb2d<41,41,36,256,false><<<dim3(2, PP), 256, SFB3_SMEM>>>(
            b3 + 4L*B3SZ, (long)PIX3, 41,
            b3 + 5L*B3SZ, b3 + 6L*B3SZ, b3 + 7L*B3SZ, (long)PIX3, ll2);
        sfb2d<72,72,34,256,true><<<dim3(4, PP), 256, SFB2_SMEM>>>(
            ll2, 72L*72, 72, lh2, hl2, hh2, 72L*72, h1);
        sfb2d<133,133,32,512,false><<<dim3(8, PP), 512, SFB1_SMEM>>>(
            h1, 134L*134, 134, lh1, hl1, hh1, 133L*133, h2);

        // ---------------- pointwise conv + add + gelu ----------------
        pw_kernel<<<2048, 256>>>(h, h2, cw + (size_t)layer * 2304,
                                 cb + (size_t)layer * 48, layer < 3 ? 1 : 0);
    }

    head_kernel<<<grd(8L * 255 * 255, 256), 256>>>(h, fc1_w, fc1_b, fc2_w, fc2_b, out);
}

// round 17
// speedup vs baseline: 1.2603x; 1.0495x over previous
#include <cuda_runtime.h>
#include <math.h>

#define BB 8
#define CC 48
#define PP (BB*CC)          // 384 planes
#define N1 256
#define O1 133
#define O2 72
#define O3 41
#define HW (N1*N1)          // 65536
#define PIX3 (O3*O3)        // 1681
#define B3SZ (PP*PIX3)      // 645504
#define P1 136              // padded row pitch for level-1 buffers (16B multiple)
#define L1PS (133L*P1)      // 18088: plane stride of ll1/lh1/hl1/hh1
#define H1PS (134L*P1)      // 18224: plane stride of h1

#define DLO_LIST { \
    -0.00107730108499558f, 0.004777257511010651f, 0.0005538422009938016f, \
    -0.031582039318031156f, 0.02752286553001629f, 0.09750160558707936f, \
    -0.12976686756709563f, -0.22626469396516913f, 0.3152503517092432f, \
    0.7511339080215775f, 0.4946238903983854f, 0.11154074335008017f }
#define DHI_LIST { \
    -0.11154074335008017f, 0.4946238903983854f, -0.7511339080215775f, \
    0.3152503517092432f, 0.22626469396516913f, -0.12976686756709563f, \
    -0.09750160558707936f, 0.02752286553001629f, 0.031582039318031156f, \
    0.0005538422009938016f, -0.004777257511010651f, -0.00107730108499558f }

// ------------------- scratch arena (static device memory) -------------------
__device__ float g_h  [PP*HW];
__device__ float g_h1 [PP*HW];      // 134x136-pitch IDWT intermediate (L2 out)
__device__ float g_h2 [PP*HW];      // L1 synthesis output (pre-pointwise)
__device__ float g_ll1[PP*133*P1];
__device__ float g_lh1[PP*133*P1];
__device__ float g_hl1[PP*133*P1];
__device__ float g_hh1[PP*133*P1];
__device__ float g_ll2[PP*O2*O2];
__device__ float g_lh2[PP*O2*O2];
__device__ float g_hl2[PP*O2*O2];
__device__ float g_hh2[PP*O2*O2];
__device__ float g_b3 [8*B3SZ];

// --------------------------- f32x2 packed helpers ---------------------------
__device__ __forceinline__ unsigned long long pack2(float x, float y) {
    unsigned long long r;
    asm("mov.b64 %0, {%1, %2};" : "=l"(r) : "f"(x), "f"(y));
    return r;
}
__device__ __forceinline__ void unpack2(unsigned long long v, float &x, float &y) {
    asm("mov.b64 {%0, %1}, %2;" : "=f"(x), "=f"(y) : "l"(v));
}
__device__ __forceinline__ unsigned long long ffma2(unsigned long long a,
                                                    unsigned long long b,
                                                    unsigned long long c) {
    unsigned long long d;
    asm("fma.rn.f32x2 %0, %1, %2, %3;" : "=l"(d) : "l"(a), "l"(b), "l"(c));
    return d;
}

__device__ __forceinline__ float gelu_f(float x) {
    return 0.5f * x * (1.0f + erff(x * 0.7071067811865475f));
}

__device__ __forceinline__ int reflect1(int i, int n) {
    i = (i < 0)  ? -1 - i : i;
    i = (i >= n) ? 2 * n - 1 - i : i;
    return i;
}

// ------------------------------ fc0 + pad -----------------------------------
__global__ void fc0_kernel(const float* __restrict__ x,
                           const float* __restrict__ w,
                           const float* __restrict__ b,
                           float* __restrict__ out) {
    int t4 = blockIdx.x * blockDim.x + threadIdx.x;
    if (t4 >= PP * HW / 4) return;
    int gidx = t4 << 2;
    int p  = gidx & (HW - 1);
    int pc = gidx >> 16;
    int ch = pc % CC, bb = pc / CC;
    int r = p >> 8, c = p & 255;
    float4 o4 = make_float4(0.f, 0.f, 0.f, 0.f);
    if (r < 255) {
        float w0 = w[ch], w1 = w[CC + ch], w2 = w[2 * CC + ch], w3 = w[3 * CC + ch];
        float bv = b[ch];
        const float* xr = x + (((size_t)bb * 255 + r) * 255 + c) * 4;
        float vals[4];
        #pragma unroll
        for (int m = 0; m < 4; m++) {
            float v = 0.f;
            if (c + m < 255) {
                float4 xv = *(const float4*)(xr + 4 * m);
                v = bv + xv.x * w0 + xv.y * w1 + xv.z * w2 + xv.w * w3;
            }
            vals[m] = v;
        }
        o4 = make_float4(vals[0], vals[1], vals[2], vals[3]);
    }
    *(float4*)(out + gidx) = o4;
}

// ---------------------- fused 2D analysis (row then col) --------------------
// VEC: interior staged via float4 (requires 16B-aligned rows: in_rs%4==0,
//      in_ps%4==0). OS = output row stride (>= OC).
template<int NR, int NC, int OR, int OC, int PADR, int K, int CH, int THREADS,
         bool VEC, int OS>
__global__ void __launch_bounds__(THREADS) afb2d(
    const float* __restrict__ in, long in_ps, int in_rs,
    float* __restrict__ ll, float* __restrict__ lh,
    float* __restrict__ hl, float* __restrict__ hh)
{
    constexpr int PW    = NC + 10 + PADR;
    constexpr int PWP   = (PW + 3) & ~1;
    constexpr int ROWS  = 2 * K + 11;
    constexpr int PITCH = (OC + 1) & ~1;
    constexpr int NPAIR = (OC + 1) / 2;
    constexpr long OPS  = (long)OR * OS;
    extern __shared__ float smem[];
    float* sIn = smem;                       // CH * PWP
    float* sLo = smem + CH * PWP;            // ROWS * PITCH
    float* sHi = sLo + ROWS * PITCH;         // ROWS * PITCH
    const float dlo[12] = DLO_LIST;
    const float dhi[12] = DHI_LIST;

    int p   = blockIdx.y;
    int k0  = blockIdx.x * K;
    int rbase = 2 * k0 - 10;
    int tid = threadIdx.x;
    const float* ip = in + (size_t)p * in_ps;

    for (int c0 = 0; c0 < ROWS; c0 += CH) {
        __syncthreads();
        if (VEC) {
            constexpr int NC4 = NC / 4;          // float4 interior count
            constexpr int BW  = PW - 4 * NC4;    // left pad + tail + right pad
            for (int e = tid; e < CH * NC4; e += THREADS) {
                int j = e / NC4, c4 = e - j * NC4;
                int rr = reflect1(rbase + c0 + j, NR);
                float4 v = *(const float4*)(ip + (size_t)rr * in_rs + 4 * c4);
                float* d = sIn + j * PWP + 10 + 4 * c4;
                d[0] = v.x; d[1] = v.y; d[2] = v.z; d[3] = v.w;
            }
            for (int e = tid; e < CH * BW; e += THREADS) {
                int j = e / BW, c = e - j * BW;
                int col = (c < 10) ? c : (c + 4 * NC4);
                int rr = reflect1(rbase + c0 + j, NR);
                int cc = reflect1(col - 10, NC);
                sIn[j * PWP + col] = ip[(size_t)rr * in_rs + cc];
            }
        } else {
            for (int e = tid; e < CH * PW; e += THREADS) {
                int j = e / PW, c = e - j * PW;
                int rr = reflect1(rbase + c0 + j, NR);
                int cc = reflect1(c - 10, NC);
                sIn[j * PWP + c] = ip[(size_t)rr * in_rs + cc];
            }
        }
        __syncthreads();
        for (int e = tid; e < CH * NPAIR; e += THREADS) {
            int j = e / NPAIR, t = e - j * NPAIR;
            int row = c0 + j;
            if (row < ROWS) {
                float v[14];
                const float2* sp = (const float2*)(sIn + j * PWP + 4 * t);
                #pragma unroll
                for (int m = 0; m < 7; m++) {
                    float2 q = sp[m];
                    v[2*m] = q.x; v[2*m+1] = q.y;
                }
                float ale = 0.f, ahe = 0.f, alo = 0.f, aho = 0.f;
                #pragma unroll
                for (int jj = 0; jj < 12; jj++) {
                    ale += v[jj]     * dlo[11 - jj];
                    ahe += v[jj]     * dhi[11 - jj];
                    alo += v[jj + 2] * dlo[11 - jj];
                    aho += v[jj + 2] * dhi[11 - jj];
                }
                *(float2*)&sLo[row * PITCH + 2*t] = make_float2(ale, alo);
                *(float2*)&sHi[row * PITCH + 2*t] = make_float2(ahe, aho);
            }
        }
    }
    __syncthreads();
    for (int e = tid; e < K * NPAIR; e += THREADS) {
        int k = e / NPAIR, cp = e - k * NPAIR;
        int kg = k0 + k;
        if (kg < OR) {
            int c = 2 * cp;
            float a0x=0,a0y=0,a1x=0,a1y=0,a2x=0,a2y=0,a3x=0,a3y=0;
            #pragma unroll
            for (int t = 0; t < 12; t++) {
                float2 a = *(const float2*)&sLo[(2*k + t) * PITCH + c];
                float2 b = *(const float2*)&sHi[(2*k + t) * PITCH + c];
                a0x += a.x * dlo[11-t]; a0y += a.y * dlo[11-t];
                a1x += a.x * dhi[11-t]; a1y += a.y * dhi[11-t];
                a2x += b.x * dlo[11-t]; a2y += b.y * dlo[11-t];
                a3x += b.x * dhi[11-t]; a3y += b.y * dhi[11-t];
            }
            size_t o = (size_t)p * OPS + (size_t)kg * OS + c;
            ll[o] = a0x; lh[o] = a1x; hl[o] = a2x; hh[o] = a3x;
            if (c + 1 < OC) {
                ll[o+1] = a0y; lh[o+1] = a1y; hl[o+1] = a2y; hh[o+1] = a3y;
            }
        }
    }
}

// ---------------------- fused 2D synthesis (col then row) -------------------
// VB: band staging via float4 interior + scalar tail (needs b_rs%4==0,
//     ll_rs%4==0, plane strides %4==0). OSW = output row stride (>= W).
template<int NIN, int M, int KO, int THREADS, bool VB, int OSW>
__global__ void __launch_bounds__(THREADS) sfb2d(
    const float* __restrict__ bll, long ll_ps, int ll_rs,
    const float* __restrict__ blh, const float* __restrict__ bhl,
    const float* __restrict__ bhh, long b_ps, int b_rs,
    float* __restrict__ out)
{
    constexpr int W   = 2 * M - 10;
    constexpr int W2  = 2 * NIN - 10;
    constexpr int RIN = KO / 2 + 6;
    constexpr int MP  = (M + 1) & ~1;
    constexpr int CP  = (M + 1) / 2;
    constexpr int UP  = M - 5;
    extern __shared__ float smem[];
    float* s0 = smem;                  // RIN*MP each
    float* s1 = s0 + RIN * MP;
    float* s2 = s1 + RIN * MP;
    float* s3 = s2 + RIN * MP;
    float* sl = s3 + RIN * MP;         // KO*MP each
    float* sh = sl + KO * MP;
    const float dlo[12] = DLO_LIST;
    const float dhi[12] = DHI_LIST;

    int p  = blockIdx.y;
    int j0 = blockIdx.x * KO;
    int r0 = j0 >> 1;
    int tid = threadIdx.x;
    const float* pll = bll + (size_t)p * ll_ps;
    const float* plh = blh + (size_t)p * b_ps;
    const float* phl = bhl + (size_t)p * b_ps;
    const float* phh = bhh + (size_t)p * b_ps;

    if (VB) {
        constexpr int M4   = M / 4;
        constexpr int TAIL = M - 4 * M4;
        for (int e = tid; e < RIN * M4; e += THREADS) {
            int r = e / M4, c4 = e - r * M4;
            int rr = r0 + r; rr = (rr > NIN - 1) ? NIN - 1 : rr;
            int se = r * MP + 4 * c4;
            float4 v;
            v = *(const float4*)(pll + (size_t)rr * ll_rs + 4 * c4);
            s0[se] = v.x; s0[se+1] = v.y; s0[se+2] = v.z; s0[se+3] = v.w;
            v = *(const float4*)(plh + (size_t)rr * b_rs + 4 * c4);
            s1[se] = v.x; s1[se+1] = v.y; s1[se+2] = v.z; s1[se+3] = v.w;
            v = *(const float4*)(phl + (size_t)rr * b_rs + 4 * c4);
            s2[se] = v.x; s2[se+1] = v.y; s2[se+2] = v.z; s2[se+3] = v.w;
            v = *(const float4*)(phh + (size_t)rr * b_rs + 4 * c4);
            s3[se] = v.x; s3[se+1] = v.y; s3[se+2] = v.z; s3[se+3] = v.w;
        }
        if (TAIL > 0) {
            for (int e = tid; e < RIN * TAIL; e += THREADS) {
                int r = e / TAIL, t = e - r * TAIL;
                int c = 4 * M4 + t;
                int rr = r0 + r; rr = (rr > NIN - 1) ? NIN - 1 : rr;
                int se = r * MP + c;
                s0[se] = pll[(size_t)rr * ll_rs + c];
                s1[se] = plh[(size_t)rr * b_rs + c];
                s2[se] = phl[(size_t)rr * b_rs + c];
                s3[se] = phh[(size_t)rr * b_rs + c];
            }
        }
    } else {
        for (int e = tid; e < RIN * M; e += THREADS) {
            int r = e / M, c = e - r * M;
            int rr = r0 + r; rr = (rr > NIN - 1) ? NIN - 1 : rr;
            int se = r * MP + c;
            s0[se] = pll[(size_t)rr * ll_rs + c];
            s1[se] = plh[(size_t)rr * b_rs + c];
            s2[se] = phl[(size_t)rr * b_rs + c];
            s3[se] = phh[(size_t)rr * b_rs + c];
        }
    }
    __syncthreads();
    for (int e = tid; e < (KO/2) * CP; e += THREADS) {
        int uj = e / CP, cp = e - uj * CP;
        int c = 2 * cp;
        float elx=0,ely=0,olx=0,oly=0,ehx=0,ehy=0,ohx=0,ohy=0;
        #pragma unroll
        for (int kk = 0; kk < 6; kk++) {
            int sb = (uj + kk) * MP + c;
            float2 a  = *(const float2*)&s0[sb];
            float2 b  = *(const float2*)&s1[sb];
            float2 g  = *(const float2*)&s2[sb];
            float2 hq = *(const float2*)&s3[sb];
            float ce = dlo[2*kk+1], co = dlo[2*kk];
            float de = dhi[2*kk+1], dq = dhi[2*kk];
            elx += a.x*ce + b.x*de;   ely += a.y*ce + b.y*de;
            olx += a.x*co + b.x*dq;   oly += a.y*co + b.y*dq;
            ehx += g.x*ce + hq.x*de;  ehy += g.y*ce + hq.y*de;
            ohx += g.x*co + hq.x*dq;  ohy += g.y*co + hq.y*dq;
        }
        int sb0 = (2*uj) * MP + c, sb1 = (2*uj + 1) * MP + c;
        if (c + 1 < M) {
            *(float2*)&sl[sb0] = make_float2(elx, ely);
            *(float2*)&sl[sb1] = make_float2(olx, oly);
            *(float2*)&sh[sb0] = make_float2(ehx, ehy);
            *(float2*)&sh[sb1] = make_float2(ohx, ohy);
        } else {
            sl[sb0] = elx; sl[sb1] = olx; sh[sb0] = ehx; sh[sb1] = ohx;
        }
    }
    __syncthreads();
    for (int e = tid; e < KO * UP; e += THREADS) {
        int j = e / UP, u = e - j * UP;
        int jg = j0 + j;
        if (jg < W2) {
            float ev = 0.f, od = 0.f;
            #pragma unroll
            for (int kk = 0; kk < 6; kk++) {
                float a = sl[j * MP + u + kk], b = sh[j * MP + u + kk];
                ev += a * dlo[2*kk+1] + b * dhi[2*kk+1];
                od += a * dlo[2*kk]   + b * dhi[2*kk];
            }
            *(float2*)&out[((size_t)p * W2 + jg) * OSW + 2*u] = make_float2(ev, od);
        }
    }
}

// --------------------- per-pixel 48x48 channel mix (41x41) ------------------
__global__ void mix_kernel(const float* __restrict__ b3in, const float* __restrict__ w,
                           float* __restrict__ b3out) {
    __shared__ float ts[384 * 18];
    __shared__ float ws[4 * 48 * 18];
    int px0 = blockIdx.x * 16;
    int band = blockIdx.y;
    int tid = threadIdx.x;
    for (int e = tid; e < 384 * 16; e += 384) {
        int plane = e >> 4, px = e & 15;
        int gp = px0 + px;
        ts[plane * 18 + px] = (gp < PIX3)
            ? b3in[(size_t)band * B3SZ + (size_t)plane * PIX3 + gp] : 0.f;
    }
    int b = tid / 48, o = tid - b * 48;
    unsigned long long acc[8];
    #pragma unroll
    for (int m = 0; m < 8; m++) acc[m] = 0ull;
    const float* wband = w + (size_t)band * 2304 * PIX3;
    for (int ic = 0; ic < 12; ic++) {
        __syncthreads();
        for (int e = tid; e < 3072; e += 384) {
            int ii = e / 768;
            int rem = e - ii * 768;
            int oo = rem >> 4, px = rem & 15;
            int gp = px0 + px;
            ws[(ii * 48 + oo) * 18 + px] = (gp < PIX3)
                ? wband[((size_t)(ic * 4 + ii) * 48 + oo) * PIX3 + gp] : 0.f;
        }
        __syncthreads();
        #pragma unroll
        for (int i = 0; i < 4; i++) {
            const unsigned long long* tr =
                (const unsigned long long*)(ts + (b * 48 + ic * 4 + i) * 18);
            const unsigned long long* wr =
                (const unsigned long long*)(ws + (i * 48 + o) * 18);
            #pragma unroll
            for (int m = 0; m < 8; m++) acc[m] = ffma2(tr[m], wr[m], acc[m]);
        }
    }
    size_t obase = (size_t)band * B3SZ + (size_t)(b * 48 + o) * PIX3 + px0;
    #pragma unroll
    for (int m = 0; m < 8; m++) {
        float x, y;
        unpack2(acc[m], x, y);
        int gp0 = px0 + 2 * m;
        if (gp0 < PIX3)     b3out[obase + 2 * m]     = x;
        if (gp0 + 1 < PIX3) b3out[obase + 2 * m + 1] = y;
    }
}

// ------------------ pointwise conv + residual add + gelu --------------------
__global__ void pw_kernel(float* __restrict__ h, const float* __restrict__ h2,
                          const float* __restrict__ cw, const float* __restrict__ cb,
                          int do_gelu) {
    __shared__ unsigned long long ws2[2304];
    __shared__ float bs[48];
    int tid = threadIdx.x;
    for (int j = tid; j < 2304; j += 256) {
        int o = j / 48, i = j - o * 48;
        float w = cw[j];
        ws2[i * 48 + o] = pack2(w, w);
    }
    if (tid < 48) bs[tid] = cb[tid];
    __syncthreads();
    int og = tid >> 6;
    int pq = tid & 63;
    int bx = blockIdx.x;
    int bb = bx >> 8;
    int p0 = ((bx & 255) << 8) + (pq << 2);
    size_t base = ((size_t)bb * CC) * HW + p0;
    unsigned long long acc[12][2];
    #pragma unroll
    for (int o = 0; o < 12; o++) {
        float b = bs[og * 12 + o];
        acc[o][0] = pack2(b, b);
        acc[o][1] = acc[o][0];
    }
    #pragma unroll 4
    for (int i = 0; i < 48; i++) {
        ulonglong2 v = *(const ulonglong2*)(h + base + (size_t)i * HW);
        #pragma unroll
        for (int o = 0; o < 12; o++) {
            unsigned long long w2 = ws2[i * 48 + og * 12 + o];
            acc[o][0] = ffma2(v.x, w2, acc[o][0]);
            acc[o][1] = ffma2(v.y, w2, acc[o][1]);
        }
    }
    __syncthreads();
    #pragma unroll
    for (int o = 0; o < 12; o++) {
        int oc = og * 12 + o;
        float4 r = *(const float4*)(h2 + base + (size_t)oc * HW);
        float a, b, c, d;
        unpack2(acc[o][0], a, b);
        unpack2(acc[o][1], c, d);
        a += r.x; b += r.y; c += r.z; d += r.w;
        if (do_gelu) { a = gelu_f(a); b = gelu_f(b); c = gelu_f(c); d = gelu_f(d); }
        *(float4*)(h + base + (size_t)oc * HW) = make_float4(a, b, c, d);
    }
}

// -------------------------- fused fc1+gelu+fc2 head --------------------------
__global__ void head_kernel(const float* __restrict__ h, const float* __restrict__ w1,
                            const float* __restrict__ b1, const float* __restrict__ w2,
                            const float* __restrict__ b2, float* __restrict__ out) {
    __shared__ unsigned long long w1s[1536];
    __shared__ float b1s[64];
    __shared__ float w2s[64];
    int tid = threadIdx.x;
    const unsigned long long* w1u = (const unsigned long long*)w1;
    for (int j = tid; j < 1536; j += 256) w1s[j] = w1u[j];
    if (tid < 64) { b1s[tid] = b1[tid]; w2s[tid] = w2[tid]; }
    __syncthreads();
    int q = blockIdx.x * 256 + tid;
    if (q >= 8 * 255 * 255) return;
    int c = q % 255;
    int t2 = q / 255;
    int r = t2 % 255;
    int bb = t2 / 255;
    size_t base = ((size_t)bb * CC) * HW + (size_t)r * 256 + c;
    unsigned long long acc[32];
    #pragma unroll
    for (int j = 0; j < 32; j++) acc[j] = pack2(b1s[2 * j], b1s[2 * j + 1]);
    #pragma unroll 4
    for (int i = 0; i < 48; i++) {
        float v = h[base + (size_t)i * HW];
        unsigned long long vv = pack2(v, v);
        #pragma unroll
        for (int j = 0; j < 32; j++) acc[j] = ffma2(vv, w1s[i * 32 + j], acc[j]);
    }
    float o = b2[0];
    #pragma unroll
    for (int j = 0; j < 32; j++) {
        float a, b;
        unpack2(acc[j], a, b);
        o += gelu_f(a) * w2s[2 * j] + gelu_f(b) * w2s[2 * j + 1];
    }
    out[q] = o;
}

// ---------------------------------- launch ----------------------------------
static inline int grd(long n, int bs) { return (int)((n + bs - 1) / bs); }

// smem sizes (bytes) matching template constexpr math
#define AFB1_SMEM ((7*278 + 2*63*134) * 4)        // 75320  (3 blocks/SM)
#define AFB2_SMEM ((5*156 + 2*59*72) * 4)         // 37104  (6 blocks/SM)
#define AFB3_SMEM ((53*94 + 2*53*42) * 4)         // 37736  (single chunk)
#define SFB3_SMEM ((4*24*42 + 2*36*42) * 4)       // 28224
#define SFB2_SMEM ((4*23*72 + 2*34*72) * 4)       // 46080
#define SFB1_SMEM ((4*22*134 + 2*32*134) * 4)     // 81472

extern "C" void kernel_launch(void* const* d_in, const int* in_sizes, int n_in,
                              void* d_out, int out_size) {
    const float* x     = (const float*)d_in[0];
    const float* fc0_w = (const float*)d_in[1];
    const float* fc0_b = (const float*)d_in[2];
    const float* wc[4] = { (const float*)d_in[3], (const float*)d_in[4],
                           (const float*)d_in[5], (const float*)d_in[6] };
    const float* cw    = (const float*)d_in[7];
    const float* cb    = (const float*)d_in[8];
    const float* fc1_w = (const float*)d_in[9];
    const float* fc1_b = (const float*)d_in[10];
    const float* fc2_w = (const float*)d_in[11];
    const float* fc2_b = (const float*)d_in[12];
    float* out = (float*)d_out;

    float *h, *h1, *h2, *ll1, *lh1, *hl1, *hh1, *ll2, *lh2, *hl2, *hh2, *b3;
    cudaGetSymbolAddress((void**)&h,   g_h);
    cudaGetSymbolAddress((void**)&h1,  g_h1);
    cudaGetSymbolAddress((void**)&h2,  g_h2);
    cudaGetSymbolAddress((void**)&ll1, g_ll1);
    cudaGetSymbolAddress((void**)&lh1, g_lh1);
    cudaGetSymbolAddress((void**)&hl1, g_hl1);
    cudaGetSymbolAddress((void**)&hh1, g_hh1);
    cudaGetSymbolAddress((void**)&ll2, g_ll2);
    cudaGetSymbolAddress((void**)&lh2, g_lh2);
    cudaGetSymbolAddress((void**)&hl2, g_hl2);
    cudaGetSymbolAddress((void**)&hh2, g_hh2);
    cudaGetSymbolAddress((void**)&b3,  g_b3);

    cudaFuncSetAttribute(afb2d<256,256,133,133,10,26,7,256,true,P1>,
                         cudaFuncAttributeMaxDynamicSharedMemorySize, AFB1_SMEM);
    cudaFuncSetAttribute(sfb2d<133,133,32,512,true,256>,
                         cudaFuncAttributeMaxDynamicSharedMemorySize, SFB1_SMEM);

    fc0_kernel<<<grd((long)PP * HW / 4, 256), 256>>>(x, fc0_w, fc0_b, h);

    for (int layer = 0; layer < 4; layer++) {
        // ---------------- forward DWT (3 fused levels) ----------------
        afb2d<256,256,133,133,10,26,7,256,true,P1><<<dim3(6, PP), 256, AFB1_SMEM>>>(
            h, (long)HW, 256, ll1, lh1, hl1, hh1);
        afb2d<133,133,72,72,11,24,5,256,true,72><<<dim3(3, PP), 256, AFB2_SMEM>>>(
            ll1, L1PS, P1, ll2, lh2, hl2, hh2);
        afb2d<72,72,41,41,10,21,53,256,true,41><<<dim3(2, PP), 256, AFB3_SMEM>>>(
            ll2, 72L*72, 72,
            b3 + 0L*B3SZ, b3 + 1L*B3SZ, b3 + 2L*B3SZ, b3 + 3L*B3SZ);

        // ---------------- coarsest-level channel mix ----------------
        mix_kernel<<<dim3(grd(PIX3,16), 4), 384>>>(b3, wc[layer], b3 + 4L*B3SZ);

        // ---------------- inverse DWT (3 fused levels) ----------------
        sfb2d<41,41,36,256,false,72><<<dim3(2, PP), 256, SFB3_SMEM>>>(
            b3 + 4L*B3SZ, (long)PIX3, 41,
            b3 + 5L*B3SZ, b3 + 6L*B3SZ, b3 + 7L*B3SZ, (long)PIX3, 41, ll2);
        sfb2d<72,72,34,256,true,P1><<<dim3(4, PP), 256, SFB2_SMEM>>>(
            ll2, 72L*72, 72, lh2, hl2, hh2, 72L*72, 72, h1);
        sfb2d<133,133,32,512,true,256><<<dim3(8, PP), 512, SFB1_SMEM>>>(
            h1, H1PS, P1, lh1, hl1, hh1, L1PS, P1, h2);

        // ---------------- pointwise conv + add + gelu ----------------
        pw_kernel<<<2048, 256>>>(h, h2, cw + (size_t)layer * 2304,
                                 cb + (size_t)layer * 48, layer < 3 ? 1 : 0);
    }

    head_kernel<<<grd(8L * 255 * 255, 256), 256>>>(h, fc1_w, fc1_b, fc2_w, fc2_b, out);
}